// round 13
// baseline (speedup 1.0000x reference)
#include <cuda_runtime.h>
#include <cuda_bf16.h>
#include <math.h>
#include <stdint.h>

#define NN 100000
#define NE 640000
#define IND 64
#define HH  128
#define NG  128

typedef unsigned long long u64;

// ---------------- scratch (static device globals) ----------------
__device__ float g_h [NN*HH];
__device__ float g_m [NN*HH];
__device__ float g_Wint[IND*HH];
__device__ float g_Wft[HH*HH];
__device__ float g_Uft[HH*HH];
__device__ float g_Wht[HH*HH];
__device__ float g_Uht[HH*HH];
__device__ float g_e  [NN];
__device__ int   g_bounds[NG+1];
// CSR scratch
__device__ int g_deg[NN];
__device__ int g_off[NN+1];
__device__ int g_csr[NE];
__device__ int g_bsum[128];
// grid barrier state
__device__ volatile int g_barcnt;
__device__ volatile int g_bargen;

__device__ __forceinline__ float sigf(float z)   { return __fdividef(1.f, 1.f + __expf(-z)); }
__device__ __forceinline__ float tanhfast(float z){ return 1.f - __fdividef(2.f, __expf(2.f*z) + 1.f); }

// ---- packed fp32x2 helpers (FFMA2) ----
__device__ __forceinline__ u64 dup2(float a){
    u64 r; asm("mov.b64 %0, {%1, %1};" : "=l"(r) : "f"(a)); return r;
}
__device__ __forceinline__ void ffma2(u64& d, u64 a, u64 b){
    asm("fma.rn.f32x2 %0, %1, %2, %0;" : "+l"(d) : "l"(a), "l"(b));
}
__device__ __forceinline__ float2 unpk(u64 v){
    float2 r; asm("mov.b64 {%0, %1}, %2;" : "=f"(r.x), "=f"(r.y) : "l"(v)); return r;
}

// ---- software grid barrier (all blocks co-resident: grid == #SM, 1 block/SM) ----
__device__ __forceinline__ void gridbar(int nblocks){
    __threadfence();
    __syncthreads();
    if (threadIdx.x == 0){
        int gen = g_bargen;
        int t = atomicAdd((int*)&g_barcnt, 1);
        if (t == nblocks - 1){
            g_barcnt = 0;
            __threadfence();
            g_bargen = gen + 1;
        } else {
            while (g_bargen == gen) { }
        }
    }
    __syncthreads();
}

// ---------------- batched transpose of the 5 weight matrices ----------------
__global__ void k_prep5(const float* __restrict__ Win, const float* __restrict__ Wf,
                        const float* __restrict__ Uf,  const float* __restrict__ Wh,
                        const float* __restrict__ Uh){
    __shared__ float t[32][33];
    int mz = blockIdx.z;
    const float* src; float* dst; int R = 128, C = 128;
    switch (mz){
        case 0: src = Win; dst = g_Wint; C = 64; break;
        case 1: src = Wf;  dst = g_Wft; break;
        case 2: src = Uf;  dst = g_Uft; break;
        case 3: src = Wh;  dst = g_Wht; break;
        default: src = Uh; dst = g_Uht; break;
    }
    int c = blockIdx.x*32 + threadIdx.x;
    int r = blockIdx.y*32 + threadIdx.y;
    if (r < R && c < C) t[threadIdx.y][threadIdx.x] = src[r*C + c];
    __syncthreads();
    int rc = blockIdx.x*32 + threadIdx.y;
    int cc = blockIdx.y*32 + threadIdx.x;
    if (rc < C && cc < R) dst[rc*R + cc] = t[threadIdx.x][threadIdx.y];
}

// ---------------- bounds + zero deg + barrier init ----------------
__global__ void k_bounds(const int* __restrict__ batch){
    int i = blockIdx.x*blockDim.x + threadIdx.x;
    if (i == 0){ g_barcnt = 0; g_bargen = 0; }
    if (i < NN) g_deg[i] = 0;
    if (i >= NN) return;
    int b = batch[i];
    if (i == 0)      { for (int g = 0;    g <= b;  g++) g_bounds[g] = 0; }
    else             { int pb = batch[i-1];
                       for (int g = pb+1; g <= b;  g++) g_bounds[g] = i; }
    if (i == NN-1)   { for (int g = b+1;  g <= NG; g++) g_bounds[g] = NN; }
}

// ---------------- CSR build ----------------
__global__ void k_hist(const int* __restrict__ dst){
    int e = blockIdx.x*blockDim.x + threadIdx.x;
    if (e < NE) atomicAdd(&g_deg[dst[e]], 1);
}
__global__ __launch_bounds__(1024) void k_scan1(){
    __shared__ int sd[1024];
    int t = threadIdx.x, i = blockIdx.x*1024 + t;
    int v = (i < NN) ? g_deg[i] : 0;
    sd[t] = v; __syncthreads();
#pragma unroll
    for (int o = 1; o < 1024; o <<= 1){
        int x = (t >= o) ? sd[t-o] : 0;
        __syncthreads();
        sd[t] += x;
        __syncthreads();
    }
    if (i < NN) g_off[i] = sd[t] - v;
    if (t == 1023) g_bsum[blockIdx.x] = sd[1023];
}
__global__ __launch_bounds__(128) void k_scan2(int nb){
    __shared__ int sd[128];
    int t = threadIdx.x;
    int v = (t < nb) ? g_bsum[t] : 0;
    sd[t] = v; __syncthreads();
#pragma unroll
    for (int o = 1; o < 128; o <<= 1){
        int x = (t >= o) ? sd[t-o] : 0;
        __syncthreads();
        sd[t] += x;
        __syncthreads();
    }
    if (t < nb) g_bsum[t] = sd[t] - v;
}
__global__ void k_scan3(){
    int i = blockIdx.x*blockDim.x + threadIdx.x;
    if (i < NN){ int o = g_off[i] + g_bsum[i >> 10]; g_off[i] = o; g_deg[i] = o; }
    if (i == 0) g_off[NN] = NE;
}
__global__ void k_fill(const int* __restrict__ src, const int* __restrict__ dst){
    int e = blockIdx.x*blockDim.x + threadIdx.x;
    if (e >= NE) return;
    int pos = atomicAdd(&g_deg[dst[e]], 1);
    g_csr[pos] = src[e];
}

// ---------------- input layer (FFMA2) ----------------
__global__ __launch_bounds__(256) void k_input(const float* __restrict__ x,
                                               const float* __restrict__ bin){
    extern __shared__ float sm[];
    float4* Ws4 = (float4*)sm;
    float4* Xs4 = (float4*)(sm + IND*HH);
    int tid = threadIdx.x;
    int jt = tid & 31, nt = tid >> 5;

    const float4* Wg = (const float4*)g_Wint;
#pragma unroll
    for (int i = 0; i < 8; i++) Ws4[tid + i*256] = Wg[tid + i*256];

    int base = blockIdx.x * 64;
    const float4* Xg = (const float4*)x;
#pragma unroll
    for (int i = 0; i < 4; i++){
        int q = tid + i*256;
        int rn = q >> 4, col = q & 15;
        int gn = base + rn;
        Xs4[q] = (gn < NN) ? Xg[gn*16 + col] : make_float4(0.f,0.f,0.f,0.f);
    }
    __syncthreads();

    u64 acc[8][2];
#pragma unroll
    for (int i = 0; i < 8; i++){ acc[i][0] = 0ull; acc[i][1] = 0ull; }

    for (int k = 0; k < IND; k += 4){
        float a[8][4];
#pragma unroll
        for (int i = 0; i < 8; i++){
            float4 t4 = Xs4[(nt*8+i)*16 + (k>>2)];
            a[i][0]=t4.x; a[i][1]=t4.y; a[i][2]=t4.z; a[i][3]=t4.w;
        }
#pragma unroll
        for (int kk = 0; kk < 4; kk++){
            ulonglong2 wv = ((const ulonglong2*)Ws4)[(k+kk)*32 + jt];
#pragma unroll
            for (int i = 0; i < 8; i++){
                u64 a2 = dup2(a[i][kk]);
                ffma2(acc[i][0], a2, wv.x);
                ffma2(acc[i][1], a2, wv.y);
            }
        }
    }
    float4 bb = ((const float4*)bin)[jt];
#pragma unroll
    for (int i = 0; i < 8; i++){
        int n = base + nt*8 + i;
        if (n < NN){
            float2 z01 = unpk(acc[i][0]);
            float2 z23 = unpk(acc[i][1]);
            float4 o;
            o.x = fmaxf(z01.x+bb.x, 0.f);
            o.y = fmaxf(z01.y+bb.y, 0.f);
            o.z = fmaxf(z23.x+bb.z, 0.f);
            o.w = fmaxf(z23.y+bb.w, 0.f);
            ((float4*)g_h)[n*32 + jt] = o;
        }
    }
}

// ---------------- fused persistent MPNN: 3 x (agg ; barrier ; MGU ; barrier) ----------------
#define SMF ((2*HH*HH + 3*64*HH) * 4)

__device__ __forceinline__ void mgu_gemm(const float4* __restrict__ As4,
    const float4* __restrict__ Bs4, const float4* __restrict__ Ws4,
    const float4* __restrict__ Us4, int nt, int jt, u64 acc[8][2])
{
#pragma unroll
    for (int i = 0; i < 8; i++){ acc[i][0] = 0ull; acc[i][1] = 0ull; }
    for (int k = 0; k < HH; k += 4){
        float a[8][4], b[8][4];
#pragma unroll
        for (int i = 0; i < 8; i++){
            float4 ta = As4[(nt*8+i)*32 + (k>>2)];
            float4 tb = Bs4[(nt*8+i)*32 + (k>>2)];
            a[i][0]=ta.x; a[i][1]=ta.y; a[i][2]=ta.z; a[i][3]=ta.w;
            b[i][0]=tb.x; b[i][1]=tb.y; b[i][2]=tb.z; b[i][3]=tb.w;
        }
#pragma unroll
        for (int kk = 0; kk < 4; kk++){
            ulonglong2 wv = ((const ulonglong2*)Ws4)[(k+kk)*32 + jt];
            ulonglong2 uv = ((const ulonglong2*)Us4)[(k+kk)*32 + jt];
#pragma unroll
            for (int i = 0; i < 8; i++){
                u64 a2 = dup2(a[i][kk]);
                u64 b2 = dup2(b[i][kk]);
                ffma2(acc[i][0], a2, wv.x);
                ffma2(acc[i][1], a2, wv.y);
                ffma2(acc[i][0], b2, uv.x);
                ffma2(acc[i][1], b2, uv.y);
            }
        }
    }
}

__device__ __forceinline__ void loadWU(float4* Ws4, float4* Us4,
    const float4* Wg, const float4* Ug, int tid)
{
#pragma unroll
    for (int i = 0; i < 16; i++){
        Ws4[tid + i*256] = __ldg(Wg + tid + i*256);
        Us4[tid + i*256] = __ldg(Ug + tid + i*256);
    }
}

// aggregation for one node (warp-cooperative, pipelined idx prefetch)
__device__ __forceinline__ void agg_node(int w, int lane){
    int s = __ldg(&g_off[w]), e = __ldg(&g_off[w+1]);
    const float4* h4 = (const float4*)g_h;
    float4 a0 = make_float4(0.f,0.f,0.f,0.f);
    float4 a1 = make_float4(0.f,0.f,0.f,0.f);
    float4 a2 = make_float4(0.f,0.f,0.f,0.f);
    float4 a3 = make_float4(0.f,0.f,0.f,0.f);
    int p = s;
    int i0=0, i1=0, i2=0, i3=0;
    bool have = (p + 3 < e);
    if (have){
        i0 = __ldg(&g_csr[p]); i1 = __ldg(&g_csr[p+1]);
        i2 = __ldg(&g_csr[p+2]); i3 = __ldg(&g_csr[p+3]);
    }
    while (have){
        float4 v0 = __ldg(h4 + (size_t)i0*32 + lane);
        float4 v1 = __ldg(h4 + (size_t)i1*32 + lane);
        float4 v2 = __ldg(h4 + (size_t)i2*32 + lane);
        float4 v3 = __ldg(h4 + (size_t)i3*32 + lane);
        p += 4;
        have = (p + 3 < e);
        if (have){
            i0 = __ldg(&g_csr[p]); i1 = __ldg(&g_csr[p+1]);
            i2 = __ldg(&g_csr[p+2]); i3 = __ldg(&g_csr[p+3]);
        }
        a0.x += v0.x; a0.y += v0.y; a0.z += v0.z; a0.w += v0.w;
        a1.x += v1.x; a1.y += v1.y; a1.z += v1.z; a1.w += v1.w;
        a2.x += v2.x; a2.y += v2.y; a2.z += v2.z; a2.w += v2.w;
        a3.x += v3.x; a3.y += v3.y; a3.z += v3.z; a3.w += v3.w;
    }
    for (; p < e; p++){
        int s0 = __ldg(&g_csr[p]);
        float4 v0 = __ldg(h4 + (size_t)s0*32 + lane);
        a0.x += v0.x; a0.y += v0.y; a0.z += v0.z; a0.w += v0.w;
    }
    a0.x += a1.x + a2.x + a3.x;
    a0.y += a1.y + a2.y + a3.y;
    a0.z += a1.z + a2.z + a3.z;
    a0.w += a1.w + a2.w + a3.w;
    ((float4*)g_m)[(size_t)w*32 + lane] = a0;
}

__global__ __launch_bounds__(256, 1) void k_mpnn(
    const float* __restrict__ bfp, const float* __restrict__ bhp, int nsm)
{
    extern __shared__ float sm[];
    float4* Ws4 = (float4*)sm;
    float4* Us4 = (float4*)(sm + HH*HH);
    float4* As4 = (float4*)(sm + 2*HH*HH);
    float4* Hs4 = (float4*)(sm + 2*HH*HH + 64*HH);
    float4* Gs4 = (float4*)(sm + 2*HH*HH + 2*64*HH);
    int tid = threadIdx.x;
    int jt = tid & 31, nt = tid >> 5;
    int lane = tid & 31, wid = tid >> 5;

    float4 bf4 = ((const float4*)bfp)[jt];
    float4 bh4 = ((const float4*)bhp)[jt];
    const float4* Ag = (const float4*)g_m;
    const float4* Hg = (const float4*)g_h;
    float* H = g_h;
    const float4* Wfg = (const float4*)g_Wft;
    const float4* Ufg = (const float4*)g_Uft;
    const float4* Whg = (const float4*)g_Wht;
    const float4* Uhg = (const float4*)g_Uht;

    int ntiles = (NN + 63) >> 6;
    int nwarp = nsm * 8;

    for (int step = 0; step < 3; step++){
        // ---- phase A: aggregation (warp per node) ----
        for (int w = blockIdx.x*8 + wid; w < NN; w += nwarp)
            agg_node(w, lane);
        gridbar(nsm);

        // ---- phase B: MGU tiles ----
        float4 pa[8], pb[8];
        {
            int base = blockIdx.x << 6;
#pragma unroll
            for (int i = 0; i < 8; i++){
                int gn = base + nt + i*8;
                if (gn < NN){ pa[i] = __ldg(Ag + (size_t)gn*32 + jt); pb[i] = __ldg(Hg + (size_t)gn*32 + jt); }
                else        { float4 z = make_float4(0.f,0.f,0.f,0.f); pa[i] = z; pb[i] = z; }
            }
        }

        for (int tile = blockIdx.x; tile < ntiles; tile += nsm){
            int base = tile << 6;
            __syncthreads();
#pragma unroll
            for (int i = 0; i < 8; i++){
                As4[tid + i*256] = pa[i];
                Hs4[tid + i*256] = pb[i];
            }
            loadWU(Ws4, Us4, Wfg, Ufg, tid);
            __syncthreads();

            int ntile = tile + nsm;
            if (ntile < ntiles){
                int nb = ntile << 6;
#pragma unroll
                for (int i = 0; i < 8; i++){
                    int gn = nb + nt + i*8;
                    if (gn < NN){ pa[i] = __ldg(Ag + (size_t)gn*32 + jt); pb[i] = __ldg(Hg + (size_t)gn*32 + jt); }
                    else        { float4 z = make_float4(0.f,0.f,0.f,0.f); pa[i] = z; pb[i] = z; }
                }
            }

            u64 acc[8][2];
            mgu_gemm(As4, Hs4, Ws4, Us4, nt, jt, acc);

            float f[8][4];
#pragma unroll
            for (int i = 0; i < 8; i++){
                float2 z01 = unpk(acc[i][0]);
                float2 z23 = unpk(acc[i][1]);
                f[i][0] = sigf(z01.x + bf4.x);
                f[i][1] = sigf(z01.y + bf4.y);
                f[i][2] = sigf(z23.x + bf4.z);
                f[i][3] = sigf(z23.y + bf4.w);
                float4 hv = Hs4[(nt*8+i)*32 + jt];
                Gs4[(nt*8+i)*32 + jt] = make_float4(f[i][0]*hv.x, f[i][1]*hv.y, f[i][2]*hv.z, f[i][3]*hv.w);
            }
            __syncthreads();

            loadWU(Ws4, Us4, Whg, Uhg, tid);
            __syncthreads();

            mgu_gemm(As4, Gs4, Ws4, Us4, nt, jt, acc);

#pragma unroll
            for (int i = 0; i < 8; i++){
                int n = base + nt*8 + i;
                if (n < NN){
                    float2 z01 = unpk(acc[i][0]);
                    float2 z23 = unpk(acc[i][1]);
                    float t0 = tanhfast(z01.x + bh4.x);
                    float t1 = tanhfast(z01.y + bh4.y);
                    float t2 = tanhfast(z23.x + bh4.z);
                    float t3 = tanhfast(z23.y + bh4.w);
                    float4 hv = Hs4[(nt*8+i)*32 + jt];
                    float4 o;
                    o.x = (1.f-f[i][0])*hv.x + f[i][0]*t0;
                    o.y = (1.f-f[i][1])*hv.y + f[i][1]*t1;
                    o.z = (1.f-f[i][2])*hv.z + f[i][2]*t2;
                    o.w = (1.f-f[i][3])*hv.w + f[i][3]*t3;
                    ((float4*)H)[(size_t)n*32 + jt] = o;
                }
            }
        }
        gridbar(nsm);
    }
}

// ---------------- fused Set2Set (3 steps LSTM+attn) + prediction ----------------
__global__ __launch_bounds__(256) void k_s2s(
    const float* __restrict__ wih, const float* __restrict__ whh,
    const float* __restrict__ bih, const float* __restrict__ bhh,
    const float* __restrict__ wp,  const float* __restrict__ bp,
    float* __restrict__ out)
{
    __shared__ __align__(16) float qs[2*HH];
    __shared__ __align__(16) float hl[HH];
    __shared__ __align__(16) float cl[HH];
    __shared__ float gt[4*HH];
    __shared__ float red[8];
    __shared__ __align__(16) float rp[8][HH];

    int g = blockIdx.x, t = threadIdx.x, wid = t >> 5, lane = t & 31;
    int s = g_bounds[g], e = g_bounds[g+1];
    const float4* h4 = (const float4*)g_h;

    if (t < HH){ hl[t] = 0.f; cl[t] = 0.f; }
    qs[t] = 0.f;
    __syncthreads();

    for (int step = 0; step < 3; step++){
        {
            const float4* qs4 = (const float4*)qs;
            const float4* hl4 = (const float4*)hl;
            float4 q0 = qs4[lane], q1 = qs4[32 + lane];
            float4 hh0 = hl4[lane];
            for (int r = wid*64; r < wid*64 + 64; r++){
                const float4* wr = (const float4*)(wih + (size_t)r*2*HH);
                const float4* hr = (const float4*)(whh + (size_t)r*HH);
                float4 w0 = __ldg(wr + lane);
                float4 w1 = __ldg(wr + 32 + lane);
                float4 h0 = __ldg(hr + lane);
                float p = w0.x*q0.x + w0.y*q0.y + w0.z*q0.z + w0.w*q0.w
                        + w1.x*q1.x + w1.y*q1.y + w1.z*q1.z + w1.w*q1.w
                        + h0.x*hh0.x + h0.y*hh0.y + h0.z*hh0.z + h0.w*hh0.w;
#pragma unroll
                for (int o = 16; o; o >>= 1) p += __shfl_xor_sync(0xffffffffu, p, o);
                if (lane == 0) gt[r] = p + __ldg(&bih[r]) + __ldg(&bhh[r]);
            }
        }
        __syncthreads();
        if (t < HH){
            float c = sigf(gt[HH+t])*cl[t] + sigf(gt[t])*tanhfast(gt[2*HH+t]);
            cl[t] = c;
            float hv = sigf(gt[3*HH+t])*tanhfast(c);
            hl[t] = hv;
            qs[t] = hv;
        }
        __syncthreads();

        float4 q4 = ((const float4*)hl)[lane];
        float lmax = -3.4e38f;
        for (int b = s + wid*4; b < e; b += 32){
            float p[4];
#pragma unroll
            for (int j = 0; j < 4; j++){
                if (b + j < e){
                    float4 x = __ldg(h4 + (size_t)(b+j)*32 + lane);
                    p[j] = x.x*q4.x + x.y*q4.y + x.z*q4.z + x.w*q4.w;
                } else p[j] = 0.f;
            }
#pragma unroll
            for (int o = 16; o; o >>= 1){
#pragma unroll
                for (int j = 0; j < 4; j++) p[j] += __shfl_xor_sync(0xffffffffu, p[j], o);
            }
#pragma unroll
            for (int j = 0; j < 4; j++){
                if (b + j < e){
                    if (lane == 0) g_e[b+j] = p[j];
                    lmax = fmaxf(lmax, p[j]);
                }
            }
        }
        if (lane == 0) red[wid] = lmax;
        __syncthreads();
        float emax = -3.4e38f;
#pragma unroll
        for (int w = 0; w < 8; w++) emax = fmaxf(emax, red[w]);
        __syncthreads();

        float lsum = 0.f;
        for (int n = s + t; n < e; n += 256){
            float w = __expf(g_e[n] - emax);
            g_e[n] = w;
            lsum += w;
        }
#pragma unroll
        for (int o = 16; o; o >>= 1) lsum += __shfl_xor_sync(0xffffffffu, lsum, o);
        if (lane == 0) red[wid] = lsum;
        __syncthreads();
        float denom = 0.f;
#pragma unroll
        for (int w = 0; w < 8; w++) denom += red[w];

        float4 racc = make_float4(0.f,0.f,0.f,0.f);
        for (int b = s + wid*4; b < e; b += 32){
#pragma unroll
            for (int j = 0; j < 4; j++){
                if (b + j < e){
                    float coef = __ldg(&g_e[b+j]);
                    float4 x = __ldg(h4 + (size_t)(b+j)*32 + lane);
                    racc.x += coef*x.x; racc.y += coef*x.y;
                    racc.z += coef*x.z; racc.w += coef*x.w;
                }
            }
        }
        ((float4*)rp[wid])[lane] = racc;
        __syncthreads();
        if (t < HH){
            float r = 0.f;
#pragma unroll
            for (int w = 0; w < 8; w++) r += rp[w][t];
            qs[HH + t] = (e > s) ? (r / denom) : 0.f;
        }
        __syncthreads();
    }

    float p = qs[t] * __ldg(&wp[t]);
#pragma unroll
    for (int o = 16; o; o >>= 1) p += __shfl_xor_sync(0xffffffffu, p, o);
    if (lane == 0) red[wid] = p;
    __syncthreads();
    if (t == 0){
        float r = 0.f;
#pragma unroll
        for (int w = 0; w < 8; w++) r += red[w];
        out[g] = r + __ldg(&bp[0]);
    }
}

// ---------------- launcher ----------------
extern "C" void kernel_launch(void* const* d_in, const int* in_sizes, int n_in,
                              void* d_out, int out_size){
    const float* x    = (const float*)d_in[0];
    const int*   ei   = (const int*)  d_in[1];
    const int*   batch= (const int*)  d_in[2];
    const float* Win  = (const float*)d_in[3];
    const float* bin  = (const float*)d_in[4];
    const float* Wf   = (const float*)d_in[5];
    const float* Uf   = (const float*)d_in[6];
    const float* bf   = (const float*)d_in[7];
    const float* Wh   = (const float*)d_in[8];
    const float* Uh   = (const float*)d_in[9];
    const float* bh   = (const float*)d_in[10];
    const float* wih  = (const float*)d_in[11];
    const float* whh  = (const float*)d_in[12];
    const float* bih  = (const float*)d_in[13];
    const float* bhh  = (const float*)d_in[14];
    const float* wp   = (const float*)d_in[15];
    const float* bp   = (const float*)d_in[16];
    float* out = (float*)d_out;

    static int nsm = 0;
    if (nsm == 0){
        cudaDeviceGetAttribute(&nsm, cudaDevAttrMultiProcessorCount, 0);
        if (nsm <= 0) nsm = 148;
    }

    cudaFuncSetAttribute(k_mpnn,  cudaFuncAttributeMaxDynamicSharedMemorySize, SMF);
    cudaFuncSetAttribute(k_input, cudaFuncAttributeMaxDynamicSharedMemorySize, 49152);

    const int* esrc = ei;
    const int* edst = ei + NE;
    const int NB1K = (NN + 1023) / 1024;

    k_prep5<<<dim3(4,4,5), dim3(32,32)>>>(Win, Wf, Uf, Wh, Uh);
    k_bounds<<<(NN+255)/256, 256>>>(batch);

    k_hist<<<(NE+255)/256, 256>>>(edst);
    k_scan1<<<NB1K, 1024>>>();
    k_scan2<<<1, 128>>>(NB1K);
    k_scan3<<<(NN+255)/256, 256>>>();
    k_fill<<<(NE+255)/256, 256>>>(esrc, edst);

    k_input<<<(NN+63)/64, 256, 49152>>>(x, bin);

    k_mpnn<<<nsm, 256, SMF>>>(bf, bh, nsm);

    k_s2s<<<NG, 256>>>(wih, whh, bih, bhh, wp, bp, out);
}

// round 14
// speedup vs baseline: 1.1506x; 1.1506x over previous
#include <cuda_runtime.h>
#include <cuda_bf16.h>
#include <math.h>
#include <stdint.h>

#define NN 100000
#define NE 640000
#define IND 64
#define HH  128
#define NG  128

typedef unsigned long long u64;

// ---------------- scratch (static device globals) ----------------
__device__ float g_h [NN*HH];
__device__ float g_m [NN*HH];
__device__ float g_Wint[IND*HH];
__device__ float g_Wft[HH*HH];
__device__ float g_Uft[HH*HH];
__device__ float g_Wht[HH*HH];
__device__ float g_Uht[HH*HH];
__device__ float g_e  [NN];
__device__ int   g_bounds[NG+1];
// CSR scratch
__device__ int g_deg[NN];
__device__ int g_off[NN+1];
__device__ int g_csr[NE];
__device__ int g_bsum[128];

__device__ __forceinline__ float sigf(float z)   { return __fdividef(1.f, 1.f + __expf(-z)); }
__device__ __forceinline__ float tanhfast(float z){ return 1.f - __fdividef(2.f, __expf(2.f*z) + 1.f); }

// ---- packed fp32x2 helpers (FFMA2) ----
__device__ __forceinline__ u64 dup2(float a){
    u64 r; asm("mov.b64 %0, {%1, %1};" : "=l"(r) : "f"(a)); return r;
}
__device__ __forceinline__ void ffma2(u64& d, u64 a, u64 b){
    asm("fma.rn.f32x2 %0, %1, %2, %0;" : "+l"(d) : "l"(a), "l"(b));
}
__device__ __forceinline__ float2 unpk(u64 v){
    float2 r; asm("mov.b64 {%0, %1}, %2;" : "=f"(r.x), "=f"(r.y) : "l"(v)); return r;
}

// ---------------- batched transpose of the 5 weight matrices ----------------
__global__ void k_prep5(const float* __restrict__ Win, const float* __restrict__ Wf,
                        const float* __restrict__ Uf,  const float* __restrict__ Wh,
                        const float* __restrict__ Uh){
    __shared__ float t[32][33];
    int mz = blockIdx.z;
    const float* src; float* dst; int R = 128, C = 128;
    switch (mz){
        case 0: src = Win; dst = g_Wint; C = 64; break;
        case 1: src = Wf;  dst = g_Wft; break;
        case 2: src = Uf;  dst = g_Uft; break;
        case 3: src = Wh;  dst = g_Wht; break;
        default: src = Uh; dst = g_Uht; break;
    }
    int c = blockIdx.x*32 + threadIdx.x;
    int r = blockIdx.y*32 + threadIdx.y;
    if (r < R && c < C) t[threadIdx.y][threadIdx.x] = src[r*C + c];
    __syncthreads();
    int rc = blockIdx.x*32 + threadIdx.y;
    int cc = blockIdx.y*32 + threadIdx.x;
    if (rc < C && cc < R) dst[rc*R + cc] = t[threadIdx.x][threadIdx.y];
}

// ---------------- bounds + zero deg ----------------
__global__ void k_bounds(const int* __restrict__ batch){
    int i = blockIdx.x*blockDim.x + threadIdx.x;
    if (i < NN) g_deg[i] = 0;
    if (i >= NN) return;
    int b = batch[i];
    if (i == 0)      { for (int g = 0;    g <= b;  g++) g_bounds[g] = 0; }
    else             { int pb = batch[i-1];
                       for (int g = pb+1; g <= b;  g++) g_bounds[g] = i; }
    if (i == NN-1)   { for (int g = b+1;  g <= NG; g++) g_bounds[g] = NN; }
}

// ---------------- CSR build ----------------
__global__ void k_hist(const int* __restrict__ dst){
    int e = blockIdx.x*blockDim.x + threadIdx.x;
    if (e < NE) atomicAdd(&g_deg[dst[e]], 1);
}
__global__ __launch_bounds__(1024) void k_scan1(){
    __shared__ int sd[1024];
    int t = threadIdx.x, i = blockIdx.x*1024 + t;
    int v = (i < NN) ? g_deg[i] : 0;
    sd[t] = v; __syncthreads();
#pragma unroll
    for (int o = 1; o < 1024; o <<= 1){
        int x = (t >= o) ? sd[t-o] : 0;
        __syncthreads();
        sd[t] += x;
        __syncthreads();
    }
    if (i < NN) g_off[i] = sd[t] - v;
    if (t == 1023) g_bsum[blockIdx.x] = sd[1023];
}
__global__ __launch_bounds__(128) void k_scan2(int nb){
    __shared__ int sd[128];
    int t = threadIdx.x;
    int v = (t < nb) ? g_bsum[t] : 0;
    sd[t] = v; __syncthreads();
#pragma unroll
    for (int o = 1; o < 128; o <<= 1){
        int x = (t >= o) ? sd[t-o] : 0;
        __syncthreads();
        sd[t] += x;
        __syncthreads();
    }
    if (t < nb) g_bsum[t] = sd[t] - v;
}
__global__ void k_scan3(){
    int i = blockIdx.x*blockDim.x + threadIdx.x;
    if (i < NN){ int o = g_off[i] + g_bsum[i >> 10]; g_off[i] = o; g_deg[i] = o; }
    if (i == 0) g_off[NN] = NE;
}
__global__ void k_fill(const int* __restrict__ src, const int* __restrict__ dst){
    int e = blockIdx.x*blockDim.x + threadIdx.x;
    if (e >= NE) return;
    int pos = atomicAdd(&g_deg[dst[e]], 1);
    g_csr[pos] = src[e];
}

// ---------------- aggregation: warp per node, unroll-4 pipelined ----------------
__global__ __launch_bounds__(256) void k_agg(){
    int w = (blockIdx.x*blockDim.x + threadIdx.x) >> 5;
    if (w >= NN) return;
    int lane = threadIdx.x & 31;
    int s = __ldg(&g_off[w]), e = __ldg(&g_off[w+1]);
    const float4* h4 = (const float4*)g_h;
    float4 a0 = make_float4(0.f,0.f,0.f,0.f);
    float4 a1 = make_float4(0.f,0.f,0.f,0.f);
    float4 a2 = make_float4(0.f,0.f,0.f,0.f);
    float4 a3 = make_float4(0.f,0.f,0.f,0.f);
    int p = s;
    int i0=0, i1=0, i2=0, i3=0;
    bool have = (p + 3 < e);
    if (have){
        i0 = __ldg(&g_csr[p]); i1 = __ldg(&g_csr[p+1]);
        i2 = __ldg(&g_csr[p+2]); i3 = __ldg(&g_csr[p+3]);
    }
    while (have){
        float4 v0 = __ldg(h4 + (size_t)i0*32 + lane);
        float4 v1 = __ldg(h4 + (size_t)i1*32 + lane);
        float4 v2 = __ldg(h4 + (size_t)i2*32 + lane);
        float4 v3 = __ldg(h4 + (size_t)i3*32 + lane);
        p += 4;
        have = (p + 3 < e);
        if (have){
            i0 = __ldg(&g_csr[p]); i1 = __ldg(&g_csr[p+1]);
            i2 = __ldg(&g_csr[p+2]); i3 = __ldg(&g_csr[p+3]);
        }
        a0.x += v0.x; a0.y += v0.y; a0.z += v0.z; a0.w += v0.w;
        a1.x += v1.x; a1.y += v1.y; a1.z += v1.z; a1.w += v1.w;
        a2.x += v2.x; a2.y += v2.y; a2.z += v2.z; a2.w += v2.w;
        a3.x += v3.x; a3.y += v3.y; a3.z += v3.z; a3.w += v3.w;
    }
    for (; p < e; p++){
        int s0 = __ldg(&g_csr[p]);
        float4 v0 = __ldg(h4 + (size_t)s0*32 + lane);
        a0.x += v0.x; a0.y += v0.y; a0.z += v0.z; a0.w += v0.w;
    }
    a0.x += a1.x + a2.x + a3.x;
    a0.y += a1.y + a2.y + a3.y;
    a0.z += a1.z + a2.z + a3.z;
    a0.w += a1.w + a2.w + a3.w;
    ((float4*)g_m)[(size_t)w*32 + lane] = a0;
}

// ---------------- input layer (FFMA2) ----------------
__global__ __launch_bounds__(256) void k_input(const float* __restrict__ x,
                                               const float* __restrict__ bin){
    extern __shared__ float sm[];
    float4* Ws4 = (float4*)sm;
    float4* Xs4 = (float4*)(sm + IND*HH);
    int tid = threadIdx.x;
    int jt = tid & 31, nt = tid >> 5;

    const float4* Wg = (const float4*)g_Wint;
#pragma unroll
    for (int i = 0; i < 8; i++) Ws4[tid + i*256] = Wg[tid + i*256];

    int base = blockIdx.x * 64;
    const float4* Xg = (const float4*)x;
#pragma unroll
    for (int i = 0; i < 4; i++){
        int q = tid + i*256;
        int rn = q >> 4, col = q & 15;
        int gn = base + rn;
        Xs4[q] = (gn < NN) ? Xg[gn*16 + col] : make_float4(0.f,0.f,0.f,0.f);
    }
    __syncthreads();

    u64 acc[8][2];
#pragma unroll
    for (int i = 0; i < 8; i++){ acc[i][0] = 0ull; acc[i][1] = 0ull; }

    for (int k = 0; k < IND; k += 4){
        float a[8][4];
#pragma unroll
        for (int i = 0; i < 8; i++){
            float4 t4 = Xs4[(nt*8+i)*16 + (k>>2)];
            a[i][0]=t4.x; a[i][1]=t4.y; a[i][2]=t4.z; a[i][3]=t4.w;
        }
#pragma unroll
        for (int kk = 0; kk < 4; kk++){
            ulonglong2 wv = ((const ulonglong2*)Ws4)[(k+kk)*32 + jt];
#pragma unroll
            for (int i = 0; i < 8; i++){
                u64 a2 = dup2(a[i][kk]);
                ffma2(acc[i][0], a2, wv.x);
                ffma2(acc[i][1], a2, wv.y);
            }
        }
    }
    float4 bb = ((const float4*)bin)[jt];
#pragma unroll
    for (int i = 0; i < 8; i++){
        int n = base + nt*8 + i;
        if (n < NN){
            float2 z01 = unpk(acc[i][0]);
            float2 z23 = unpk(acc[i][1]);
            float4 o;
            o.x = fmaxf(z01.x+bb.x, 0.f);
            o.y = fmaxf(z01.y+bb.y, 0.f);
            o.z = fmaxf(z23.x+bb.z, 0.f);
            o.w = fmaxf(z23.y+bb.w, 0.f);
            ((float4*)g_h)[n*32 + jt] = o;
        }
    }
}

// ---------------- fused MGU step: both dual-GEMMs per tile ----------------
#define SMF ((2*HH*HH + 3*64*HH) * 4)

__device__ __forceinline__ void loadWU(float4* Ws4, float4* Us4,
    const float4* Wg, const float4* Ug, int tid)
{
#pragma unroll
    for (int i = 0; i < 16; i++){
        Ws4[tid + i*256] = __ldg(Wg + tid + i*256);
        Us4[tid + i*256] = __ldg(Ug + tid + i*256);
    }
}

__device__ __forceinline__ void mgu_gemm(const float4* __restrict__ As4,
    const float4* __restrict__ Bs4, const float4* __restrict__ Ws4,
    const float4* __restrict__ Us4, int nt, int jt, u64 acc[8][2])
{
#pragma unroll
    for (int i = 0; i < 8; i++){ acc[i][0] = 0ull; acc[i][1] = 0ull; }
    for (int k = 0; k < HH; k += 4){
        float a[8][4], b[8][4];
#pragma unroll
        for (int i = 0; i < 8; i++){
            float4 ta = As4[(nt*8+i)*32 + (k>>2)];
            float4 tb = Bs4[(nt*8+i)*32 + (k>>2)];
            a[i][0]=ta.x; a[i][1]=ta.y; a[i][2]=ta.z; a[i][3]=ta.w;
            b[i][0]=tb.x; b[i][1]=tb.y; b[i][2]=tb.z; b[i][3]=tb.w;
        }
#pragma unroll
        for (int kk = 0; kk < 4; kk++){
            ulonglong2 wv = ((const ulonglong2*)Ws4)[(k+kk)*32 + jt];
            ulonglong2 uv = ((const ulonglong2*)Us4)[(k+kk)*32 + jt];
#pragma unroll
            for (int i = 0; i < 8; i++){
                u64 a2 = dup2(a[i][kk]);
                u64 b2 = dup2(b[i][kk]);
                ffma2(acc[i][0], a2, wv.x);
                ffma2(acc[i][1], a2, wv.y);
                ffma2(acc[i][0], b2, uv.x);
                ffma2(acc[i][1], b2, uv.y);
            }
        }
    }
}

__global__ __launch_bounds__(256, 1) void k_mgu(
    const float* __restrict__ A, float* __restrict__ H,
    const float* __restrict__ bfp, const float* __restrict__ bhp)
{
    extern __shared__ float sm[];
    float4* Ws4 = (float4*)sm;
    float4* Us4 = (float4*)(sm + HH*HH);
    float4* As4 = (float4*)(sm + 2*HH*HH);
    float4* Hs4 = (float4*)(sm + 2*HH*HH + 64*HH);
    float4* Gs4 = (float4*)(sm + 2*HH*HH + 2*64*HH);
    int tid = threadIdx.x;
    int jt = tid & 31, nt = tid >> 5;

    float4 bf4 = ((const float4*)bfp)[jt];
    float4 bh4 = ((const float4*)bhp)[jt];
    const float4* Ag = (const float4*)A;
    const float4* Hg = (const float4*)H;
    const float4* Wfg = (const float4*)g_Wft;
    const float4* Ufg = (const float4*)g_Uft;
    const float4* Whg = (const float4*)g_Wht;
    const float4* Uhg = (const float4*)g_Uht;

    int ntiles = (NN + 63) >> 6;

    float4 pa[8], pb[8];
    {
        int base = blockIdx.x << 6;
#pragma unroll
        for (int i = 0; i < 8; i++){
            int gn = base + nt + i*8;
            if (gn < NN){ pa[i] = __ldg(Ag + (size_t)gn*32 + jt); pb[i] = __ldg(Hg + (size_t)gn*32 + jt); }
            else        { float4 z = make_float4(0.f,0.f,0.f,0.f); pa[i] = z; pb[i] = z; }
        }
    }

    for (int tile = blockIdx.x; tile < ntiles; tile += gridDim.x){
        int base = tile << 6;
        __syncthreads();
#pragma unroll
        for (int i = 0; i < 8; i++){
            As4[tid + i*256] = pa[i];
            Hs4[tid + i*256] = pb[i];
        }
        loadWU(Ws4, Us4, Wfg, Ufg, tid);
        __syncthreads();

        int ntile = tile + gridDim.x;
        if (ntile < ntiles){
            int nb = ntile << 6;
#pragma unroll
            for (int i = 0; i < 8; i++){
                int gn = nb + nt + i*8;
                if (gn < NN){ pa[i] = __ldg(Ag + (size_t)gn*32 + jt); pb[i] = __ldg(Hg + (size_t)gn*32 + jt); }
                else        { float4 z = make_float4(0.f,0.f,0.f,0.f); pa[i] = z; pb[i] = z; }
            }
        }

        u64 acc[8][2];
        mgu_gemm(As4, Hs4, Ws4, Us4, nt, jt, acc);

        float f[8][4];
#pragma unroll
        for (int i = 0; i < 8; i++){
            float2 z01 = unpk(acc[i][0]);
            float2 z23 = unpk(acc[i][1]);
            f[i][0] = sigf(z01.x + bf4.x);
            f[i][1] = sigf(z01.y + bf4.y);
            f[i][2] = sigf(z23.x + bf4.z);
            f[i][3] = sigf(z23.y + bf4.w);
            float4 hv = Hs4[(nt*8+i)*32 + jt];
            Gs4[(nt*8+i)*32 + jt] = make_float4(f[i][0]*hv.x, f[i][1]*hv.y, f[i][2]*hv.z, f[i][3]*hv.w);
        }
        __syncthreads();

        loadWU(Ws4, Us4, Whg, Uhg, tid);
        __syncthreads();

        mgu_gemm(As4, Gs4, Ws4, Us4, nt, jt, acc);

#pragma unroll
        for (int i = 0; i < 8; i++){
            int n = base + nt*8 + i;
            if (n < NN){
                float2 z01 = unpk(acc[i][0]);
                float2 z23 = unpk(acc[i][1]);
                float t0 = tanhfast(z01.x + bh4.x);
                float t1 = tanhfast(z01.y + bh4.y);
                float t2 = tanhfast(z23.x + bh4.z);
                float t3 = tanhfast(z23.y + bh4.w);
                float4 hv = Hs4[(nt*8+i)*32 + jt];
                float4 o;
                o.x = (1.f-f[i][0])*hv.x + f[i][0]*t0;
                o.y = (1.f-f[i][1])*hv.y + f[i][1]*t1;
                o.z = (1.f-f[i][2])*hv.z + f[i][2]*t2;
                o.w = (1.f-f[i][3])*hv.w + f[i][3]*t3;
                ((float4*)H)[(size_t)n*32 + jt] = o;
            }
        }
    }
}

// ---------------- fused Set2Set (3 steps LSTM+attn) + prediction ----------------
__global__ __launch_bounds__(256) void k_s2s(
    const float* __restrict__ wih, const float* __restrict__ whh,
    const float* __restrict__ bih, const float* __restrict__ bhh,
    const float* __restrict__ wp,  const float* __restrict__ bp,
    float* __restrict__ out)
{
    __shared__ __align__(16) float qs[2*HH];
    __shared__ __align__(16) float hl[HH];
    __shared__ __align__(16) float cl[HH];
    __shared__ float gt[4*HH];
    __shared__ float red[8];
    __shared__ __align__(16) float rp[8][HH];

    int g = blockIdx.x, t = threadIdx.x, wid = t >> 5, lane = t & 31;
    int s = g_bounds[g], e = g_bounds[g+1];
    const float4* h4 = (const float4*)g_h;

    if (t < HH){ hl[t] = 0.f; cl[t] = 0.f; }
    qs[t] = 0.f;
    __syncthreads();

    for (int step = 0; step < 3; step++){
        {
            const float4* qs4 = (const float4*)qs;
            const float4* hl4 = (const float4*)hl;
            float4 q0 = qs4[lane], q1 = qs4[32 + lane];
            float4 hh0 = hl4[lane];
            for (int r = wid*64; r < wid*64 + 64; r++){
                const float4* wr = (const float4*)(wih + (size_t)r*2*HH);
                const float4* hr = (const float4*)(whh + (size_t)r*HH);
                float4 w0 = __ldg(wr + lane);
                float4 w1 = __ldg(wr + 32 + lane);
                float4 h0 = __ldg(hr + lane);
                float p = w0.x*q0.x + w0.y*q0.y + w0.z*q0.z + w0.w*q0.w
                        + w1.x*q1.x + w1.y*q1.y + w1.z*q1.z + w1.w*q1.w
                        + h0.x*hh0.x + h0.y*hh0.y + h0.z*hh0.z + h0.w*hh0.w;
#pragma unroll
                for (int o = 16; o; o >>= 1) p += __shfl_xor_sync(0xffffffffu, p, o);
                if (lane == 0) gt[r] = p + __ldg(&bih[r]) + __ldg(&bhh[r]);
            }
        }
        __syncthreads();
        if (t < HH){
            float c = sigf(gt[HH+t])*cl[t] + sigf(gt[t])*tanhfast(gt[2*HH+t]);
            cl[t] = c;
            float hv = sigf(gt[3*HH+t])*tanhfast(c);
            hl[t] = hv;
            qs[t] = hv;
        }
        __syncthreads();

        float4 q4 = ((const float4*)hl)[lane];
        float lmax = -3.4e38f;
        for (int b = s + wid*4; b < e; b += 32){
            float p[4];
#pragma unroll
            for (int j = 0; j < 4; j++){
                if (b + j < e){
                    float4 x = __ldg(h4 + (size_t)(b+j)*32 + lane);
                    p[j] = x.x*q4.x + x.y*q4.y + x.z*q4.z + x.w*q4.w;
                } else p[j] = 0.f;
            }
#pragma unroll
            for (int o = 16; o; o >>= 1){
#pragma unroll
                for (int j = 0; j < 4; j++) p[j] += __shfl_xor_sync(0xffffffffu, p[j], o);
            }
#pragma unroll
            for (int j = 0; j < 4; j++){
                if (b + j < e){
                    if (lane == 0) g_e[b+j] = p[j];
                    lmax = fmaxf(lmax, p[j]);
                }
            }
        }
        if (lane == 0) red[wid] = lmax;
        __syncthreads();
        float emax = -3.4e38f;
#pragma unroll
        for (int w = 0; w < 8; w++) emax = fmaxf(emax, red[w]);
        __syncthreads();

        float lsum = 0.f;
        for (int n = s + t; n < e; n += 256){
            float w = __expf(g_e[n] - emax);
            g_e[n] = w;
            lsum += w;
        }
#pragma unroll
        for (int o = 16; o; o >>= 1) lsum += __shfl_xor_sync(0xffffffffu, lsum, o);
        if (lane == 0) red[wid] = lsum;
        __syncthreads();
        float denom = 0.f;
#pragma unroll
        for (int w = 0; w < 8; w++) denom += red[w];

        float4 racc = make_float4(0.f,0.f,0.f,0.f);
        for (int b = s + wid*4; b < e; b += 32){
#pragma unroll
            for (int j = 0; j < 4; j++){
                if (b + j < e){
                    float coef = __ldg(&g_e[b+j]);
                    float4 x = __ldg(h4 + (size_t)(b+j)*32 + lane);
                    racc.x += coef*x.x; racc.y += coef*x.y;
                    racc.z += coef*x.z; racc.w += coef*x.w;
                }
            }
        }
        ((float4*)rp[wid])[lane] = racc;
        __syncthreads();
        if (t < HH){
            float r = 0.f;
#pragma unroll
            for (int w = 0; w < 8; w++) r += rp[w][t];
            qs[HH + t] = (e > s) ? (r / denom) : 0.f;
        }
        __syncthreads();
    }

    float p = qs[t] * __ldg(&wp[t]);
#pragma unroll
    for (int o = 16; o; o >>= 1) p += __shfl_xor_sync(0xffffffffu, p, o);
    if (lane == 0) red[wid] = p;
    __syncthreads();
    if (t == 0){
        float r = 0.f;
#pragma unroll
        for (int w = 0; w < 8; w++) r += red[w];
        out[g] = r + __ldg(&bp[0]);
    }
}

// ---------------- launcher ----------------
extern "C" void kernel_launch(void* const* d_in, const int* in_sizes, int n_in,
                              void* d_out, int out_size){
    const float* x    = (const float*)d_in[0];
    const int*   ei   = (const int*)  d_in[1];
    const int*   batch= (const int*)  d_in[2];
    const float* Win  = (const float*)d_in[3];
    const float* bin  = (const float*)d_in[4];
    const float* Wf   = (const float*)d_in[5];
    const float* Uf   = (const float*)d_in[6];
    const float* bf   = (const float*)d_in[7];
    const float* Wh   = (const float*)d_in[8];
    const float* Uh   = (const float*)d_in[9];
    const float* bh   = (const float*)d_in[10];
    const float* wih  = (const float*)d_in[11];
    const float* whh  = (const float*)d_in[12];
    const float* bih  = (const float*)d_in[13];
    const float* bhh  = (const float*)d_in[14];
    const float* wp   = (const float*)d_in[15];
    const float* bp   = (const float*)d_in[16];
    float* out = (float*)d_out;

    float *p_m, *p_h;
    cudaGetSymbolAddress((void**)&p_m, g_m);
    cudaGetSymbolAddress((void**)&p_h, g_h);

    // static side stream + events (created on first, uncaptured call)
    static cudaStream_t s2 = nullptr;
    static cudaEvent_t evFork = nullptr, evJoin = nullptr;
    if (!s2){
        cudaStreamCreateWithFlags(&s2, cudaStreamNonBlocking);
        cudaEventCreateWithFlags(&evFork, cudaEventDisableTiming);
        cudaEventCreateWithFlags(&evJoin, cudaEventDisableTiming);
    }

    cudaFuncSetAttribute(k_mgu,   cudaFuncAttributeMaxDynamicSharedMemorySize, SMF);
    cudaFuncSetAttribute(k_input, cudaFuncAttributeMaxDynamicSharedMemorySize, 49152);

    const int* esrc = ei;
    const int* edst = ei + NE;
    const int NB1K = (NN + 1023) / 1024;

    k_prep5<<<dim3(4,4,5), dim3(32,32)>>>(Win, Wf, Uf, Wh, Uh);
    k_bounds<<<(NN+255)/256, 256>>>(batch);

    // fork: input layer on side stream, CSR build on main stream
    cudaEventRecord(evFork, 0);
    cudaStreamWaitEvent(s2, evFork, 0);
    k_input<<<(NN+63)/64, 256, 49152, s2>>>(x, bin);
    cudaEventRecord(evJoin, s2);

    k_hist<<<(NE+255)/256, 256>>>(edst);
    k_scan1<<<NB1K, 1024>>>();
    k_scan2<<<1, 128>>>(NB1K);
    k_scan3<<<(NN+255)/256, 256>>>();
    k_fill<<<(NE+255)/256, 256>>>(esrc, edst);

    // join before the MPNN loop
    cudaStreamWaitEvent(0, evJoin, 0);

    for (int step = 0; step < 3; step++){
        k_agg<<<(NN*32 + 255)/256, 256>>>();
        k_mgu<<<152, 256, SMF>>>(p_m, p_h, bf, bh);
    }

    k_s2s<<<NG, 256>>>(wih, whh, bih, bhh, wp, bp, out);
}

// round 15
// speedup vs baseline: 1.5130x; 1.3150x over previous
#include <cuda_runtime.h>
#include <cuda_bf16.h>
#include <math.h>
#include <stdint.h>

#define NN 100000
#define NE 640000
#define IND 64
#define HH  128
#define NG  128

typedef unsigned long long u64;

// ---------------- scratch (static device globals) ----------------
__device__ float g_h [NN*HH];
__device__ float g_m [NN*HH];
__device__ float g_Wint[IND*HH];
__device__ float g_e  [NN];
__device__ int   g_bounds[NG+1];
// bf16 hi/lo weight images: [128 n][264 k] (k = W|U concat + 8 pad), per gate
#define WKW 132            // words (uint32 = 2 bf16) per row
__device__ uint32_t g_VFh[HH*WKW];
__device__ uint32_t g_VFl[HH*WKW];
__device__ uint32_t g_VHh[HH*WKW];
__device__ uint32_t g_VHl[HH*WKW];
// CSR scratch
__device__ int g_deg[NN];
__device__ int g_off[NN+1];
__device__ int g_csr[NE];
__device__ int g_bsum[128];

__device__ __forceinline__ float sigf(float z)   { return __fdividef(1.f, 1.f + __expf(-z)); }
__device__ __forceinline__ float tanhfast(float z){ return 1.f - __fdividef(2.f, __expf(2.f*z) + 1.f); }

// ---- packed fp32x2 helpers (FFMA2, for input layer) ----
__device__ __forceinline__ u64 dup2(float a){
    u64 r; asm("mov.b64 %0, {%1, %1};" : "=l"(r) : "f"(a)); return r;
}
__device__ __forceinline__ void ffma2(u64& d, u64 a, u64 b){
    asm("fma.rn.f32x2 %0, %1, %2, %0;" : "+l"(d) : "l"(a), "l"(b));
}
__device__ __forceinline__ float2 unpk(u64 v){
    float2 r; asm("mov.b64 {%0, %1}, %2;" : "=f"(r.x), "=f"(r.y) : "l"(v)); return r;
}

// ---- bf16 pack/resid (verified in R5) ----
__device__ __forceinline__ uint32_t pack_hi(float lo, float hi_e){
    uint32_t r; asm("cvt.rn.bf16x2.f32 %0, %1, %2;" : "=r"(r) : "f"(hi_e), "f"(lo)); return r;
}
__device__ __forceinline__ float2 resid(float vx, float vy, uint32_t hp){
    float r0 = __uint_as_float(hp << 16);
    float r1 = __uint_as_float(hp & 0xFFFF0000u);
    return make_float2(vx - r0, vy - r1);
}

// ---- mma.sync bf16 (fragment mapping verified in R5) ----
__device__ __forceinline__ void mma_bf16(float* c, const uint32_t* a, uint32_t b0, uint32_t b1){
    asm volatile("mma.sync.aligned.m16n8k16.row.col.f32.bf16.bf16.f32 "
        "{%0,%1,%2,%3}, {%4,%5,%6,%7}, {%8,%9}, {%0,%1,%2,%3};"
        : "+f"(c[0]), "+f"(c[1]), "+f"(c[2]), "+f"(c[3])
        : "r"(a[0]), "r"(a[1]), "r"(a[2]), "r"(a[3]), "r"(b0), "r"(b1));
}

// ---- cp.async ----
__device__ __forceinline__ void cpa16(uint32_t saddr, const void* g){
    asm volatile("cp.async.cg.shared.global [%0], [%1], 16;" :: "r"(saddr), "l"(g) : "memory");
}
#define CPA_COMMIT() asm volatile("cp.async.commit_group;" ::: "memory")
#define CPA_WAIT0()  asm volatile("cp.async.wait_group 0;" ::: "memory")

// ---------------- Win transpose ----------------
__global__ void k_prepin(const float* __restrict__ Win){
    __shared__ float t[32][33];
    int c = blockIdx.x*32 + threadIdx.x;
    int r = blockIdx.y*32 + threadIdx.y;
    if (r < 128 && c < 64) t[threadIdx.y][threadIdx.x] = Win[r*64 + c];
    __syncthreads();
    int rc = blockIdx.x*32 + threadIdx.y;
    int cc = blockIdx.y*32 + threadIdx.x;
    if (rc < 64 && cc < 128) g_Wint[rc*128 + cc] = t[threadIdx.x][threadIdx.y];
}

// ---------------- weight prep: bf16 hi/lo images [128][264] per gate ----------------
__global__ void k_prepw(const float* __restrict__ Wf, const float* __restrict__ Uf,
                        const float* __restrict__ Wh, const float* __restrict__ Uh){
    int idx = blockIdx.x*blockDim.x + threadIdx.x;
    if (idx >= 2*HH*2*WKW) return;          // elements = 2 gates x 128 n x 264 k
    int gate = idx / (HH*2*WKW);
    int rem  = idx % (HH*2*WKW);
    int n = rem / (2*WKW);
    int k = rem % (2*WKW);
    float v = 0.f;
    if (k < 128)      v = (gate ? Wh : Wf)[n*128 + k];
    else if (k < 256) v = (gate ? Uh : Uf)[n*128 + (k-128)];
    __nv_bfloat16 hb = __float2bfloat16(v);
    float lo = v - __bfloat162float(hb);
    __nv_bfloat16 lb = __float2bfloat16(lo);
    __nv_bfloat16* H = (__nv_bfloat16*)(gate ? g_VHh : g_VFh);
    __nv_bfloat16* L = (__nv_bfloat16*)(gate ? g_VHl : g_VFl);
    H[n*2*WKW + k] = hb;
    L[n*2*WKW + k] = lb;
}

// ---------------- bounds + zero deg ----------------
__global__ void k_bounds(const int* __restrict__ batch){
    int i = blockIdx.x*blockDim.x + threadIdx.x;
    if (i < NN) g_deg[i] = 0;
    if (i >= NN) return;
    int b = batch[i];
    if (i == 0)      { for (int g = 0;    g <= b;  g++) g_bounds[g] = 0; }
    else             { int pb = batch[i-1];
                       for (int g = pb+1; g <= b;  g++) g_bounds[g] = i; }
    if (i == NN-1)   { for (int g = b+1;  g <= NG; g++) g_bounds[g] = NN; }
}

// ---------------- CSR build ----------------
__global__ void k_hist(const int* __restrict__ dst){
    int e = blockIdx.x*blockDim.x + threadIdx.x;
    if (e < NE) atomicAdd(&g_deg[dst[e]], 1);
}
__global__ __launch_bounds__(1024) void k_scan1(){
    __shared__ int sd[1024];
    int t = threadIdx.x, i = blockIdx.x*1024 + t;
    int v = (i < NN) ? g_deg[i] : 0;
    sd[t] = v; __syncthreads();
#pragma unroll
    for (int o = 1; o < 1024; o <<= 1){
        int x = (t >= o) ? sd[t-o] : 0;
        __syncthreads();
        sd[t] += x;
        __syncthreads();
    }
    if (i < NN) g_off[i] = sd[t] - v;
    if (t == 1023) g_bsum[blockIdx.x] = sd[1023];
}
__global__ __launch_bounds__(128) void k_scan2(int nb){
    __shared__ int sd[128];
    int t = threadIdx.x;
    int v = (t < nb) ? g_bsum[t] : 0;
    sd[t] = v; __syncthreads();
#pragma unroll
    for (int o = 1; o < 128; o <<= 1){
        int x = (t >= o) ? sd[t-o] : 0;
        __syncthreads();
        sd[t] += x;
        __syncthreads();
    }
    if (t < nb) g_bsum[t] = sd[t] - v;
}
__global__ void k_scan3(){
    int i = blockIdx.x*blockDim.x + threadIdx.x;
    if (i < NN){ int o = g_off[i] + g_bsum[i >> 10]; g_off[i] = o; g_deg[i] = o; }
    if (i == 0) g_off[NN] = NE;
}
__global__ void k_fill(const int* __restrict__ src, const int* __restrict__ dst){
    int e = blockIdx.x*blockDim.x + threadIdx.x;
    if (e >= NE) return;
    int pos = atomicAdd(&g_deg[dst[e]], 1);
    g_csr[pos] = src[e];
}

// ---------------- aggregation: warp per node, unroll-2 ----------------
__global__ __launch_bounds__(256) void k_agg(){
    int w = (blockIdx.x*blockDim.x + threadIdx.x) >> 5;
    if (w >= NN) return;
    int lane = threadIdx.x & 31;
    int s = __ldg(&g_off[w]), e = __ldg(&g_off[w+1]);
    const float4* h4 = (const float4*)g_h;
    float4 acc = make_float4(0.f,0.f,0.f,0.f);
    int p = s;
    for (; p + 1 < e; p += 2){
        int s0 = __ldg(&g_csr[p]);
        int s1 = __ldg(&g_csr[p+1]);
        float4 v0 = __ldg(h4 + (size_t)s0*32 + lane);
        float4 v1 = __ldg(h4 + (size_t)s1*32 + lane);
        acc.x += v0.x; acc.y += v0.y; acc.z += v0.z; acc.w += v0.w;
        acc.x += v1.x; acc.y += v1.y; acc.z += v1.z; acc.w += v1.w;
    }
    if (p < e){
        int s0 = __ldg(&g_csr[p]);
        float4 v0 = __ldg(h4 + (size_t)s0*32 + lane);
        acc.x += v0.x; acc.y += v0.y; acc.z += v0.z; acc.w += v0.w;
    }
    ((float4*)g_m)[(size_t)w*32 + lane] = acc;
}

// ---------------- input layer (FFMA2) ----------------
__global__ __launch_bounds__(256) void k_input(const float* __restrict__ x,
                                               const float* __restrict__ bin){
    extern __shared__ float sm[];
    float4* Ws4 = (float4*)sm;
    float4* Xs4 = (float4*)(sm + IND*HH);
    int tid = threadIdx.x;
    int jt = tid & 31, nt = tid >> 5;

    const float4* Wg = (const float4*)g_Wint;
#pragma unroll
    for (int i = 0; i < 8; i++) Ws4[tid + i*256] = Wg[tid + i*256];

    int base = blockIdx.x * 64;
    const float4* Xg = (const float4*)x;
#pragma unroll
    for (int i = 0; i < 4; i++){
        int q = tid + i*256;
        int rn = q >> 4, col = q & 15;
        int gn = base + rn;
        Xs4[q] = (gn < NN) ? Xg[gn*16 + col] : make_float4(0.f,0.f,0.f,0.f);
    }
    __syncthreads();

    u64 acc[8][2];
#pragma unroll
    for (int i = 0; i < 8; i++){ acc[i][0] = 0ull; acc[i][1] = 0ull; }

    for (int k = 0; k < IND; k += 4){
        float a[8][4];
#pragma unroll
        for (int i = 0; i < 8; i++){
            float4 t4 = Xs4[(nt*8+i)*16 + (k>>2)];
            a[i][0]=t4.x; a[i][1]=t4.y; a[i][2]=t4.z; a[i][3]=t4.w;
        }
#pragma unroll
        for (int kk = 0; kk < 4; kk++){
            ulonglong2 wv = ((const ulonglong2*)Ws4)[(k+kk)*32 + jt];
#pragma unroll
            for (int i = 0; i < 8; i++){
                u64 a2 = dup2(a[i][kk]);
                ffma2(acc[i][0], a2, wv.x);
                ffma2(acc[i][1], a2, wv.y);
            }
        }
    }
    float4 bb = ((const float4*)bin)[jt];
#pragma unroll
    for (int i = 0; i < 8; i++){
        int n = base + nt*8 + i;
        if (n < NN){
            float2 z01 = unpk(acc[i][0]);
            float2 z23 = unpk(acc[i][1]);
            float4 o;
            o.x = fmaxf(z01.x+bb.x, 0.f);
            o.y = fmaxf(z01.y+bb.y, 0.f);
            o.z = fmaxf(z23.x+bb.z, 0.f);
            o.w = fmaxf(z23.y+bb.w, 0.f);
            ((float4*)g_h)[n*32 + jt] = o;
        }
    }
}

// ---------------- fused MGU step via bf16-split mma.sync ----------------
// SMEM words: Whi[128*132] Wlo[128*132] Ahi[64*132] Alo[64*132] = 50688 words
#define OFF_WHI 0
#define OFF_WLO (HH*WKW)
#define OFF_AHI (2*HH*WKW)
#define OFF_ALO (2*HH*WKW + 64*WKW)
#define SMW_TOT (2*HH*WKW + 2*64*WKW)
#define SMF2 (SMW_TOT*4)
#define WCP 4224   // 16B chunks per weight image (128*132*4/16)

__global__ __launch_bounds__(256, 1) void k_mgu_mma(
    const float* __restrict__ bfp, const float* __restrict__ bhp)
{
    extern __shared__ uint32_t smw[];
    uint32_t* Whi = smw + OFF_WHI;
    uint32_t* Wlo = smw + OFF_WLO;
    uint32_t* Ahi = smw + OFF_AHI;
    uint32_t* Alo = smw + OFF_ALO;
    uint32_t whi_sa = (uint32_t)__cvta_generic_to_shared(Whi);
    uint32_t wlo_sa = (uint32_t)__cvta_generic_to_shared(Wlo);

    int tid = threadIdx.x;
    int lane = tid & 31, wid = tid >> 5;
    int wr = wid & 3;          // m-row group (16 rows)
    int wc = wid >> 2;         // col group (64 cols)
    int r0 = lane >> 2;        // 0..7
    int tig = lane & 3;        // 0..3

    const float4* Mg = (const float4*)g_m;
    const float4* Hg = (const float4*)g_h;

    int ntiles = (NN + 63) >> 6;

    for (int tile = blockIdx.x; tile < ntiles; tile += gridDim.x){
        int base = tile << 6;
        __syncthreads();   // previous tile fully done (incl. staging reads)

        // issue phase-1 weight copies (f-gate)
#pragma unroll
        for (int i = 0; i < 17; i++){
            int q = tid + i*256;
            if (q < WCP){
                cpa16(whi_sa + q*16, (const char*)g_VFh + q*16);
                cpa16(wlo_sa + q*16, (const char*)g_VFl + q*16);
            }
        }
        CPA_COMMIT();

        // A-tile conversion: [m|h] fp32 -> bf16 hi/lo, rows 0..63, k 0..255
#pragma unroll
        for (int i = 0; i < 16; i++){
            int q = tid + i*256;           // 0..4095
            int row = q >> 6, c4 = q & 63; // c4: float4 col 0..63
            int gn = base + row;
            float4 v = make_float4(0.f,0.f,0.f,0.f);
            if (gn < NN) v = (c4 < 32) ? __ldg(Mg + (size_t)gn*32 + c4)
                                       : __ldg(Hg + (size_t)gn*32 + (c4-32));
            uint32_t h0 = pack_hi(v.x, v.y);
            uint32_t h1 = pack_hi(v.z, v.w);
            float2 l0 = resid(v.x, v.y, h0);
            float2 l1 = resid(v.z, v.w, h1);
            int wbase = row*WKW + 2*c4;
            Ahi[wbase]   = h0;
            Ahi[wbase+1] = h1;
            Alo[wbase]   = pack_hi(l0.x, l0.y);
            Alo[wbase+1] = pack_hi(l1.x, l1.y);
        }
        CPA_WAIT0();
        __syncthreads();

        // ---- GEMM1: z1 = [m|h] @ [Wf|Uf]^T ----
        float c[8][4];
#pragma unroll
        for (int t = 0; t < 8; t++){ c[t][0]=0.f; c[t][1]=0.f; c[t][2]=0.f; c[t][3]=0.f; }
        {
            int ra = (wr*16 + r0)*WKW;
            int rb = ra + 8*WKW;
#pragma unroll 4
            for (int ks = 0; ks < 16; ks++){
                int kw = ks*8 + tig;
                uint32_t ah[4], al[4];
                ah[0] = Ahi[ra + kw];     ah[1] = Ahi[rb + kw];
                ah[2] = Ahi[ra + kw + 4]; ah[3] = Ahi[rb + kw + 4];
                al[0] = Alo[ra + kw];     al[1] = Alo[rb + kw];
                al[2] = Alo[ra + kw + 4]; al[3] = Alo[rb + kw + 4];
#pragma unroll
                for (int t = 0; t < 8; t++){
                    int n = (wc*64 + t*8 + r0)*WKW;
                    uint32_t bh0 = Whi[n + kw], bh1 = Whi[n + kw + 4];
                    uint32_t bl0 = Wlo[n + kw], bl1 = Wlo[n + kw + 4];
                    mma_bf16(c[t], ah, bh0, bh1);
                    mma_bf16(c[t], al, bh0, bh1);
                    mma_bf16(c[t], ah, bl0, bl1);
                }
            }
        }
        __syncthreads();   // all warps done reading phase-1 weights

        // issue phase-2 weight copies (h-gate)
#pragma unroll
        for (int i = 0; i < 17; i++){
            int q = tid + i*256;
            if (q < WCP){
                cpa16(whi_sa + q*16, (const char*)g_VHh + q*16);
                cpa16(wlo_sa + q*16, (const char*)g_VHl + q*16);
            }
        }
        CPA_COMMIT();

        // ---- epilogue 1: f = sigmoid(z1+bf); g = f*h -> A g-half (bf16 hi/lo) ----
        int gra = base + wr*16 + r0;
        int grb = gra + 8;
        float fk[8][4], hk[8][4];
#pragma unroll
        for (int t = 0; t < 8; t++){
            int col = wc*64 + t*8 + tig*2;
            float2 bz = __ldg((const float2*)&bfp[col]);
            float2 ha = (gra < NN) ? __ldg((const float2*)&g_h[(size_t)gra*HH + col]) : make_float2(0.f,0.f);
            float2 hb = (grb < NN) ? __ldg((const float2*)&g_h[(size_t)grb*HH + col]) : make_float2(0.f,0.f);
            fk[t][0] = sigf(c[t][0] + bz.x);
            fk[t][1] = sigf(c[t][1] + bz.y);
            fk[t][2] = sigf(c[t][2] + bz.x);
            fk[t][3] = sigf(c[t][3] + bz.y);
            hk[t][0] = ha.x; hk[t][1] = ha.y; hk[t][2] = hb.x; hk[t][3] = hb.y;
            float ga0 = fk[t][0]*ha.x, ga1 = fk[t][1]*ha.y;
            float gb0 = fk[t][2]*hb.x, gb1 = fk[t][3]*hb.y;
            int lra = (wr*16 + r0)*WKW + 64 + (col >> 1);
            int lrb = lra + 8*WKW;
            uint32_t pa = pack_hi(ga0, ga1);
            uint32_t pb = pack_hi(gb0, gb1);
            float2 la = resid(ga0, ga1, pa);
            float2 lb = resid(gb0, gb1, pb);
            Ahi[lra] = pa; Alo[lra] = pack_hi(la.x, la.y);
            Ahi[lrb] = pb; Alo[lrb] = pack_hi(lb.x, lb.y);
        }
        CPA_WAIT0();
        __syncthreads();   // g visible + phase-2 weights landed

        // ---- GEMM2: z2 = [m|g] @ [Wh|Uh]^T ----
#pragma unroll
        for (int t = 0; t < 8; t++){ c[t][0]=0.f; c[t][1]=0.f; c[t][2]=0.f; c[t][3]=0.f; }
        {
            int ra = (wr*16 + r0)*WKW;
            int rb = ra + 8*WKW;
#pragma unroll 4
            for (int ks = 0; ks < 16; ks++){
                int kw = ks*8 + tig;
                uint32_t ah[4], al[4];
                ah[0] = Ahi[ra + kw];     ah[1] = Ahi[rb + kw];
                ah[2] = Ahi[ra + kw + 4]; ah[3] = Ahi[rb + kw + 4];
                al[0] = Alo[ra + kw];     al[1] = Alo[rb + kw];
                al[2] = Alo[ra + kw + 4]; al[3] = Alo[rb + kw + 4];
#pragma unroll
                for (int t = 0; t < 8; t++){
                    int n = (wc*64 + t*8 + r0)*WKW;
                    uint32_t bh0 = Whi[n + kw], bh1 = Whi[n + kw + 4];
                    uint32_t bl0 = Wlo[n + kw], bl1 = Wlo[n + kw + 4];
                    mma_bf16(c[t], ah, bh0, bh1);
                    mma_bf16(c[t], al, bh0, bh1);
                    mma_bf16(c[t], ah, bl0, bl1);
                }
            }
        }
        __syncthreads();   // A reads done before staging overwrite

        // ---- epilogue 2: h_new = (1-f)*h + f*tanh(z2+bh) -> stage in SMEM ----
        float* S = (float*)Ahi;   // reuse, stride WKW floats per row
#pragma unroll
        for (int t = 0; t < 8; t++){
            int col = wc*64 + t*8 + tig*2;
            float2 bz = __ldg((const float2*)&bhp[col]);
            float t0 = tanhfast(c[t][0] + bz.x);
            float t1 = tanhfast(c[t][1] + bz.y);
            float t2 = tanhfast(c[t][2] + bz.x);
            float t3 = tanhfast(c[t][3] + bz.y);
            int lra = (wr*16 + r0)*WKW + col;
            int lrb = lra + 8*WKW;
            *(float2*)&S[lra] = make_float2((1.f-fk[t][0])*hk[t][0] + fk[t][0]*t0,
                                            (1.f-fk[t][1])*hk[t][1] + fk[t][1]*t1);
            *(float2*)&S[lrb] = make_float2((1.f-fk[t][2])*hk[t][2] + fk[t][2]*t2,
                                            (1.f-fk[t][3])*hk[t][3] + fk[t][3]*t3);
        }
        __syncthreads();

        // coalesced store h_new
#pragma unroll
        for (int i = 0; i < 8; i++){
            int q = tid + i*256;           // 0..2047
            int row = q >> 5, c4 = q & 31;
            int gn = base + row;
            if (gn < NN){
                float4 v = *(float4*)&S[row*WKW + c4*4];
                ((float4*)g_h)[(size_t)gn*32 + c4] = v;
            }
        }
    }
}

// ---------------- fused Set2Set (3 steps LSTM+attn) + prediction ----------------
__global__ __launch_bounds__(256) void k_s2s(
    const float* __restrict__ wih, const float* __restrict__ whh,
    const float* __restrict__ bih, const float* __restrict__ bhh,
    const float* __restrict__ wp,  const float* __restrict__ bp,
    float* __restrict__ out)
{
    __shared__ __align__(16) float qs[2*HH];
    __shared__ __align__(16) float hl[HH];
    __shared__ __align__(16) float cl[HH];
    __shared__ float gt[4*HH];
    __shared__ float red[8];
    __shared__ __align__(16) float rp[8][HH];

    int g = blockIdx.x, t = threadIdx.x, wid = t >> 5, lane = t & 31;
    int s = g_bounds[g], e = g_bounds[g+1];
    const float4* h4 = (const float4*)g_h;

    if (t < HH){ hl[t] = 0.f; cl[t] = 0.f; }
    qs[t] = 0.f;
    __syncthreads();

    for (int step = 0; step < 3; step++){
        {
            const float4* qs4 = (const float4*)qs;
            const float4* hl4 = (const float4*)hl;
            float4 q0 = qs4[lane], q1 = qs4[32 + lane];
            float4 hh0 = hl4[lane];
            for (int r = wid*64; r < wid*64 + 64; r++){
                const float4* wr = (const float4*)(wih + (size_t)r*2*HH);
                const float4* hr = (const float4*)(whh + (size_t)r*HH);
                float4 w0 = __ldg(wr + lane);
                float4 w1 = __ldg(wr + 32 + lane);
                float4 h0 = __ldg(hr + lane);
                float p = w0.x*q0.x + w0.y*q0.y + w0.z*q0.z + w0.w*q0.w
                        + w1.x*q1.x + w1.y*q1.y + w1.z*q1.z + w1.w*q1.w
                        + h0.x*hh0.x + h0.y*hh0.y + h0.z*hh0.z + h0.w*hh0.w;
#pragma unroll
                for (int o = 16; o; o >>= 1) p += __shfl_xor_sync(0xffffffffu, p, o);
                if (lane == 0) gt[r] = p + __ldg(&bih[r]) + __ldg(&bhh[r]);
            }
        }
        __syncthreads();
        if (t < HH){
            float c = sigf(gt[HH+t])*cl[t] + sigf(gt[t])*tanhfast(gt[2*HH+t]);
            cl[t] = c;
            float hv = sigf(gt[3*HH+t])*tanhfast(c);
            hl[t] = hv;
            qs[t] = hv;
        }
        __syncthreads();

        float4 q4 = ((const float4*)hl)[lane];
        float lmax = -3.4e38f;
        for (int b = s + wid*4; b < e; b += 32){
            float p[4];
#pragma unroll
            for (int j = 0; j < 4; j++){
                if (b + j < e){
                    float4 x = __ldg(h4 + (size_t)(b+j)*32 + lane);
                    p[j] = x.x*q4.x + x.y*q4.y + x.z*q4.z + x.w*q4.w;
                } else p[j] = 0.f;
            }
#pragma unroll
            for (int o = 16; o; o >>= 1){
#pragma unroll
                for (int j = 0; j < 4; j++) p[j] += __shfl_xor_sync(0xffffffffu, p[j], o);
            }
#pragma unroll
            for (int j = 0; j < 4; j++){
                if (b + j < e){
                    if (lane == 0) g_e[b+j] = p[j];
                    lmax = fmaxf(lmax, p[j]);
                }
            }
        }
        if (lane == 0) red[wid] = lmax;
        __syncthreads();
        float emax = -3.4e38f;
#pragma unroll
        for (int w = 0; w < 8; w++) emax = fmaxf(emax, red[w]);
        __syncthreads();

        float lsum = 0.f;
        for (int n = s + t; n < e; n += 256){
            float w = __expf(g_e[n] - emax);
            g_e[n] = w;
            lsum += w;
        }
#pragma unroll
        for (int o = 16; o; o >>= 1) lsum += __shfl_xor_sync(0xffffffffu, lsum, o);
        if (lane == 0) red[wid] = lsum;
        __syncthreads();
        float denom = 0.f;
#pragma unroll
        for (int w = 0; w < 8; w++) denom += red[w];

        float4 racc = make_float4(0.f,0.f,0.f,0.f);
        for (int b = s + wid*4; b < e; b += 32){
#pragma unroll
            for (int j = 0; j < 4; j++){
                if (b + j < e){
                    float coef = __ldg(&g_e[b+j]);
                    float4 x = __ldg(h4 + (size_t)(b+j)*32 + lane);
                    racc.x += coef*x.x; racc.y += coef*x.y;
                    racc.z += coef*x.z; racc.w += coef*x.w;
                }
            }
        }
        ((float4*)rp[wid])[lane] = racc;
        __syncthreads();
        if (t < HH){
            float r = 0.f;
#pragma unroll
            for (int w = 0; w < 8; w++) r += rp[w][t];
            qs[HH + t] = (e > s) ? (r / denom) : 0.f;
        }
        __syncthreads();
    }

    float p = qs[t] * __ldg(&wp[t]);
#pragma unroll
    for (int o = 16; o; o >>= 1) p += __shfl_xor_sync(0xffffffffu, p, o);
    if (lane == 0) red[wid] = p;
    __syncthreads();
    if (t == 0){
        float r = 0.f;
#pragma unroll
        for (int w = 0; w < 8; w++) r += red[w];
        out[g] = r + __ldg(&bp[0]);
    }
}

// ---------------- launcher ----------------
extern "C" void kernel_launch(void* const* d_in, const int* in_sizes, int n_in,
                              void* d_out, int out_size){
    const float* x    = (const float*)d_in[0];
    const int*   ei   = (const int*)  d_in[1];
    const int*   batch= (const int*)  d_in[2];
    const float* Win  = (const float*)d_in[3];
    const float* bin  = (const float*)d_in[4];
    const float* Wf   = (const float*)d_in[5];
    const float* Uf   = (const float*)d_in[6];
    const float* bf   = (const float*)d_in[7];
    const float* Wh   = (const float*)d_in[8];
    const float* Uh   = (const float*)d_in[9];
    const float* bh   = (const float*)d_in[10];
    const float* wih  = (const float*)d_in[11];
    const float* whh  = (const float*)d_in[12];
    const float* bih  = (const float*)d_in[13];
    const float* bhh  = (const float*)d_in[14];
    const float* wp   = (const float*)d_in[15];
    const float* bp   = (const float*)d_in[16];
    float* out = (float*)d_out;

    cudaFuncSetAttribute(k_mgu_mma, cudaFuncAttributeMaxDynamicSharedMemorySize, SMF2);
    cudaFuncSetAttribute(k_input,   cudaFuncAttributeMaxDynamicSharedMemorySize, 49152);

    const int* esrc = ei;
    const int* edst = ei + NE;
    const int NB1K = (NN + 1023) / 1024;

    k_prepin<<<dim3(2,4), dim3(32,32)>>>(Win);
    k_prepw<<<(2*HH*2*WKW + 255)/256, 256>>>(Wf, Uf, Wh, Uh);
    k_bounds<<<(NN+255)/256, 256>>>(batch);

    k_hist<<<(NE+255)/256, 256>>>(edst);
    k_scan1<<<NB1K, 1024>>>();
    k_scan2<<<1, 128>>>(NB1K);
    k_scan3<<<(NN+255)/256, 256>>>();
    k_fill<<<(NE+255)/256, 256>>>(esrc, edst);

    k_input<<<(NN+63)/64, 256, 49152>>>(x, bin);

    for (int step = 0; step < 3; step++){
        k_agg<<<(NN*32 + 255)/256, 256>>>();
        k_mgu_mma<<<152, 256, SMF2>>>(bf, bh);
    }

    k_s2s<<<NG, 256>>>(wih, whh, bih, bhh, wp, bp, out);
}

// round 16
// speedup vs baseline: 1.5609x; 1.0316x over previous
#include <cuda_runtime.h>
#include <cuda_bf16.h>
#include <math.h>
#include <stdint.h>

#define NN 100000
#define NE 640000
#define IND 64
#define HH  128
#define NG  128

typedef unsigned long long u64;

// ---------------- scratch (static device globals) ----------------
__device__ float g_h [NN*HH];
__device__ float g_m [NN*HH];
__device__ float g_Wint[IND*HH];
__device__ float g_e  [NN];
__device__ int   g_bounds[NG+1];
// bf16 hi/lo weight images: [128 n][264 k] (k = W|U concat + 8 pad), per gate
#define WKW 132            // words (uint32 = 2 bf16) per row
__device__ uint32_t g_VFh[HH*WKW];
__device__ uint32_t g_VFl[HH*WKW];
__device__ uint32_t g_VHh[HH*WKW];
__device__ uint32_t g_VHl[HH*WKW];
// CSR scratch
__device__ int g_deg[NN];
__device__ int g_off[NN+1];
__device__ int g_csr[NE];
__device__ int g_bsum[128];

__device__ __forceinline__ float sigf(float z)   { return __fdividef(1.f, 1.f + __expf(-z)); }
__device__ __forceinline__ float tanhfast(float z){ return 1.f - __fdividef(2.f, __expf(2.f*z) + 1.f); }

// ---- packed fp32x2 helpers (FFMA2, for input layer) ----
__device__ __forceinline__ u64 dup2(float a){
    u64 r; asm("mov.b64 %0, {%1, %1};" : "=l"(r) : "f"(a)); return r;
}
__device__ __forceinline__ void ffma2(u64& d, u64 a, u64 b){
    asm("fma.rn.f32x2 %0, %1, %2, %0;" : "+l"(d) : "l"(a), "l"(b));
}
__device__ __forceinline__ float2 unpk(u64 v){
    float2 r; asm("mov.b64 {%0, %1}, %2;" : "=f"(r.x), "=f"(r.y) : "l"(v)); return r;
}

// ---- bf16 pack/resid ----
__device__ __forceinline__ uint32_t pack_hi(float lo, float hi_e){
    uint32_t r; asm("cvt.rn.bf16x2.f32 %0, %1, %2;" : "=r"(r) : "f"(hi_e), "f"(lo)); return r;
}
__device__ __forceinline__ float2 resid(float vx, float vy, uint32_t hp){
    float r0 = __uint_as_float(hp << 16);
    float r1 = __uint_as_float(hp & 0xFFFF0000u);
    return make_float2(vx - r0, vy - r1);
}

// ---- mma.sync bf16 ----
__device__ __forceinline__ void mma_bf16(float* c, const uint32_t* a, uint32_t b0, uint32_t b1){
    asm volatile("mma.sync.aligned.m16n8k16.row.col.f32.bf16.bf16.f32 "
        "{%0,%1,%2,%3}, {%4,%5,%6,%7}, {%8,%9}, {%0,%1,%2,%3};"
        : "+f"(c[0]), "+f"(c[1]), "+f"(c[2]), "+f"(c[3])
        : "r"(a[0]), "r"(a[1]), "r"(a[2]), "r"(a[3]), "r"(b0), "r"(b1));
}

// ---- ldmatrix x4 (sm_75 baseline PTX) ----
__device__ __forceinline__ void ldmx4(uint32_t* r, uint32_t saddr){
    asm volatile("ldmatrix.sync.aligned.m8n8.x4.shared.b16 {%0,%1,%2,%3}, [%4];"
        : "=r"(r[0]), "=r"(r[1]), "=r"(r[2]), "=r"(r[3]) : "r"(saddr));
}

// ---- cp.async ----
__device__ __forceinline__ void cpa16(uint32_t saddr, const void* g){
    asm volatile("cp.async.cg.shared.global [%0], [%1], 16;" :: "r"(saddr), "l"(g) : "memory");
}
#define CPA_COMMIT() asm volatile("cp.async.commit_group;" ::: "memory")
#define CPA_WAIT0()  asm volatile("cp.async.wait_group 0;" ::: "memory")

// ---------------- Win transpose ----------------
__global__ void k_prepin(const float* __restrict__ Win){
    __shared__ float t[32][33];
    int c = blockIdx.x*32 + threadIdx.x;
    int r = blockIdx.y*32 + threadIdx.y;
    if (r < 128 && c < 64) t[threadIdx.y][threadIdx.x] = Win[r*64 + c];
    __syncthreads();
    int rc = blockIdx.x*32 + threadIdx.y;
    int cc = blockIdx.y*32 + threadIdx.x;
    if (rc < 64 && cc < 128) g_Wint[rc*128 + cc] = t[threadIdx.x][threadIdx.y];
}

// ---------------- weight prep: bf16 hi/lo images [128][264] per gate ----------------
__global__ void k_prepw(const float* __restrict__ Wf, const float* __restrict__ Uf,
                        const float* __restrict__ Wh, const float* __restrict__ Uh){
    int idx = blockIdx.x*blockDim.x + threadIdx.x;
    if (idx >= 2*HH*2*WKW) return;
    int gate = idx / (HH*2*WKW);
    int rem  = idx % (HH*2*WKW);
    int n = rem / (2*WKW);
    int k = rem % (2*WKW);
    float v = 0.f;
    if (k < 128)      v = (gate ? Wh : Wf)[n*128 + k];
    else if (k < 256) v = (gate ? Uh : Uf)[n*128 + (k-128)];
    __nv_bfloat16 hb = __float2bfloat16(v);
    float lo = v - __bfloat162float(hb);
    __nv_bfloat16 lb = __float2bfloat16(lo);
    __nv_bfloat16* H = (__nv_bfloat16*)(gate ? g_VHh : g_VFh);
    __nv_bfloat16* L = (__nv_bfloat16*)(gate ? g_VHl : g_VFl);
    H[n*2*WKW + k] = hb;
    L[n*2*WKW + k] = lb;
}

// ---------------- bounds + zero deg ----------------
__global__ void k_bounds(const int* __restrict__ batch){
    int i = blockIdx.x*blockDim.x + threadIdx.x;
    if (i < NN) g_deg[i] = 0;
    if (i >= NN) return;
    int b = batch[i];
    if (i == 0)      { for (int g = 0;    g <= b;  g++) g_bounds[g] = 0; }
    else             { int pb = batch[i-1];
                       for (int g = pb+1; g <= b;  g++) g_bounds[g] = i; }
    if (i == NN-1)   { for (int g = b+1;  g <= NG; g++) g_bounds[g] = NN; }
}

// ---------------- CSR build ----------------
__global__ void k_hist(const int* __restrict__ dst){
    int e = blockIdx.x*blockDim.x + threadIdx.x;
    if (e < NE) atomicAdd(&g_deg[dst[e]], 1);
}
__global__ __launch_bounds__(1024) void k_scan1(){
    __shared__ int sd[1024];
    int t = threadIdx.x, i = blockIdx.x*1024 + t;
    int v = (i < NN) ? g_deg[i] : 0;
    sd[t] = v; __syncthreads();
#pragma unroll
    for (int o = 1; o < 1024; o <<= 1){
        int x = (t >= o) ? sd[t-o] : 0;
        __syncthreads();
        sd[t] += x;
        __syncthreads();
    }
    if (i < NN) g_off[i] = sd[t] - v;
    if (t == 1023) g_bsum[blockIdx.x] = sd[1023];
}
__global__ __launch_bounds__(128) void k_scan2(int nb){
    __shared__ int sd[128];
    int t = threadIdx.x;
    int v = (t < nb) ? g_bsum[t] : 0;
    sd[t] = v; __syncthreads();
#pragma unroll
    for (int o = 1; o < 128; o <<= 1){
        int x = (t >= o) ? sd[t-o] : 0;
        __syncthreads();
        sd[t] += x;
        __syncthreads();
    }
    if (t < nb) g_bsum[t] = sd[t] - v;
}
__global__ void k_scan3(){
    int i = blockIdx.x*blockDim.x + threadIdx.x;
    if (i < NN){ int o = g_off[i] + g_bsum[i >> 10]; g_off[i] = o; g_deg[i] = o; }
    if (i == 0) g_off[NN] = NE;
}
__global__ void k_fill(const int* __restrict__ src, const int* __restrict__ dst){
    int e = blockIdx.x*blockDim.x + threadIdx.x;
    if (e >= NE) return;
    int pos = atomicAdd(&g_deg[dst[e]], 1);
    g_csr[pos] = src[e];
}

// ---------------- aggregation: warp per node, unroll-2 ----------------
__global__ __launch_bounds__(256) void k_agg(){
    int w = (blockIdx.x*blockDim.x + threadIdx.x) >> 5;
    if (w >= NN) return;
    int lane = threadIdx.x & 31;
    int s = __ldg(&g_off[w]), e = __ldg(&g_off[w+1]);
    const float4* h4 = (const float4*)g_h;
    float4 acc = make_float4(0.f,0.f,0.f,0.f);
    int p = s;
    for (; p + 1 < e; p += 2){
        int s0 = __ldg(&g_csr[p]);
        int s1 = __ldg(&g_csr[p+1]);
        float4 v0 = __ldg(h4 + (size_t)s0*32 + lane);
        float4 v1 = __ldg(h4 + (size_t)s1*32 + lane);
        acc.x += v0.x; acc.y += v0.y; acc.z += v0.z; acc.w += v0.w;
        acc.x += v1.x; acc.y += v1.y; acc.z += v1.z; acc.w += v1.w;
    }
    if (p < e){
        int s0 = __ldg(&g_csr[p]);
        float4 v0 = __ldg(h4 + (size_t)s0*32 + lane);
        acc.x += v0.x; acc.y += v0.y; acc.z += v0.z; acc.w += v0.w;
    }
    ((float4*)g_m)[(size_t)w*32 + lane] = acc;
}

// ---------------- input layer (FFMA2) ----------------
__global__ __launch_bounds__(256) void k_input(const float* __restrict__ x,
                                               const float* __restrict__ bin){
    extern __shared__ float sm[];
    float4* Ws4 = (float4*)sm;
    float4* Xs4 = (float4*)(sm + IND*HH);
    int tid = threadIdx.x;
    int jt = tid & 31, nt = tid >> 5;

    const float4* Wg = (const float4*)g_Wint;
#pragma unroll
    for (int i = 0; i < 8; i++) Ws4[tid + i*256] = Wg[tid + i*256];

    int base = blockIdx.x * 64;
    const float4* Xg = (const float4*)x;
#pragma unroll
    for (int i = 0; i < 4; i++){
        int q = tid + i*256;
        int rn = q >> 4, col = q & 15;
        int gn = base + rn;
        Xs4[q] = (gn < NN) ? Xg[gn*16 + col] : make_float4(0.f,0.f,0.f,0.f);
    }
    __syncthreads();

    u64 acc[8][2];
#pragma unroll
    for (int i = 0; i < 8; i++){ acc[i][0] = 0ull; acc[i][1] = 0ull; }

    for (int k = 0; k < IND; k += 4){
        float a[8][4];
#pragma unroll
        for (int i = 0; i < 8; i++){
            float4 t4 = Xs4[(nt*8+i)*16 + (k>>2)];
            a[i][0]=t4.x; a[i][1]=t4.y; a[i][2]=t4.z; a[i][3]=t4.w;
        }
#pragma unroll
        for (int kk = 0; kk < 4; kk++){
            ulonglong2 wv = ((const ulonglong2*)Ws4)[(k+kk)*32 + jt];
#pragma unroll
            for (int i = 0; i < 8; i++){
                u64 a2 = dup2(a[i][kk]);
                ffma2(acc[i][0], a2, wv.x);
                ffma2(acc[i][1], a2, wv.y);
            }
        }
    }
    float4 bb = ((const float4*)bin)[jt];
#pragma unroll
    for (int i = 0; i < 8; i++){
        int n = base + nt*8 + i;
        if (n < NN){
            float2 z01 = unpk(acc[i][0]);
            float2 z23 = unpk(acc[i][1]);
            float4 o;
            o.x = fmaxf(z01.x+bb.x, 0.f);
            o.y = fmaxf(z01.y+bb.y, 0.f);
            o.z = fmaxf(z23.x+bb.z, 0.f);
            o.w = fmaxf(z23.y+bb.w, 0.f);
            ((float4*)g_h)[n*32 + jt] = o;
        }
    }
}

// ---------------- fused MGU step via bf16-split mma.sync + ldmatrix ----------------
#define OFF_WHI 0
#define OFF_WLO (HH*WKW)
#define OFF_AHI (2*HH*WKW)
#define OFF_ALO (2*HH*WKW + 64*WKW)
#define SMW_TOT (2*HH*WKW + 2*64*WKW)
#define SMF2 (SMW_TOT*4)
#define WCP 4224   // 16B chunks per weight image (128*132*4/16)

__global__ __launch_bounds__(256, 1) void k_mgu_mma(
    const float* __restrict__ bfp, const float* __restrict__ bhp)
{
    extern __shared__ uint32_t smw[];
    uint32_t* Whi = smw + OFF_WHI;
    uint32_t* Wlo = smw + OFF_WLO;
    uint32_t* Ahi = smw + OFF_AHI;
    uint32_t* Alo = smw + OFF_ALO;
    uint32_t whi_sa = (uint32_t)__cvta_generic_to_shared(Whi);
    uint32_t wlo_sa = (uint32_t)__cvta_generic_to_shared(Wlo);
    uint32_t ahi_sa = (uint32_t)__cvta_generic_to_shared(Ahi);
    uint32_t alo_sa = (uint32_t)__cvta_generic_to_shared(Alo);

    int tid = threadIdx.x;
    int lane = tid & 31, wid = tid >> 5;
    int wr = wid & 3;          // m-row group (16 rows)
    int wc = wid >> 2;         // col group (64 cols)
    int r0 = lane >> 2;        // 0..7
    int tig = lane & 3;        // 0..3

    // ldmatrix lane addressing (tile-invariant)
    int j8 = lane >> 3, l7 = lane & 7;
    uint32_t a_row = (uint32_t)(wr*16 + ((j8 & 1) << 3) + l7);
    uint32_t a_off = (a_row*WKW + ((j8 >> 1) << 2)) * 4u;
    uint32_t aHad = ahi_sa + a_off;
    uint32_t aLad = alo_sa + a_off;
    uint32_t bHad[4], bLad[4];
#pragma unroll
    for (int p = 0; p < 4; p++){
        uint32_t b_row = (uint32_t)(wc*64 + (2*p + (j8 >> 1))*8 + l7);
        uint32_t b_off = (b_row*WKW + ((j8 & 1) << 2)) * 4u;
        bHad[p] = whi_sa + b_off;
        bLad[p] = wlo_sa + b_off;
    }

    const float4* Mg = (const float4*)g_m;
    const float4* Hg = (const float4*)g_h;

    int ntiles = (NN + 63) >> 6;

    for (int tile = blockIdx.x; tile < ntiles; tile += gridDim.x){
        int base = tile << 6;
        __syncthreads();   // previous tile fully done

        // issue phase-1 weight copies (f-gate)
#pragma unroll
        for (int i = 0; i < 17; i++){
            int q = tid + i*256;
            if (q < WCP){
                cpa16(whi_sa + q*16, (const char*)g_VFh + q*16);
                cpa16(wlo_sa + q*16, (const char*)g_VFl + q*16);
            }
        }
        CPA_COMMIT();

        // A-tile conversion: [m|h] fp32 -> bf16 hi/lo
#pragma unroll
        for (int i = 0; i < 16; i++){
            int q = tid + i*256;
            int row = q >> 6, c4 = q & 63;
            int gn = base + row;
            float4 v = make_float4(0.f,0.f,0.f,0.f);
            if (gn < NN) v = (c4 < 32) ? __ldg(Mg + (size_t)gn*32 + c4)
                                       : __ldg(Hg + (size_t)gn*32 + (c4-32));
            uint32_t h0 = pack_hi(v.x, v.y);
            uint32_t h1 = pack_hi(v.z, v.w);
            float2 l0 = resid(v.x, v.y, h0);
            float2 l1 = resid(v.z, v.w, h1);
            int wbase = row*WKW + 2*c4;
            Ahi[wbase]   = h0;
            Ahi[wbase+1] = h1;
            Alo[wbase]   = pack_hi(l0.x, l0.y);
            Alo[wbase+1] = pack_hi(l1.x, l1.y);
        }
        CPA_WAIT0();
        __syncthreads();

        // ---- GEMM1: z1 = [m|h] @ [Wf|Uf]^T ----
        float c[8][4];
#pragma unroll
        for (int t = 0; t < 8; t++){ c[t][0]=0.f; c[t][1]=0.f; c[t][2]=0.f; c[t][3]=0.f; }
#pragma unroll 4
        for (int ks = 0; ks < 16; ks++){
            uint32_t ko = (uint32_t)(ks*32);
            uint32_t ah[4], al[4];
            ldmx4(ah, aHad + ko);
            ldmx4(al, aLad + ko);
#pragma unroll
            for (int p = 0; p < 4; p++){
                uint32_t bh[4], bl[4];
                ldmx4(bh, bHad[p] + ko);
                ldmx4(bl, bLad[p] + ko);
                mma_bf16(c[2*p],   ah, bh[0], bh[1]);
                mma_bf16(c[2*p],   al, bh[0], bh[1]);
                mma_bf16(c[2*p],   ah, bl[0], bl[1]);
                mma_bf16(c[2*p+1], ah, bh[2], bh[3]);
                mma_bf16(c[2*p+1], al, bh[2], bh[3]);
                mma_bf16(c[2*p+1], ah, bl[2], bl[3]);
            }
        }
        __syncthreads();   // all warps done reading phase-1 weights

        // issue phase-2 weight copies (h-gate)
#pragma unroll
        for (int i = 0; i < 17; i++){
            int q = tid + i*256;
            if (q < WCP){
                cpa16(whi_sa + q*16, (const char*)g_VHh + q*16);
                cpa16(wlo_sa + q*16, (const char*)g_VHl + q*16);
            }
        }
        CPA_COMMIT();

        // ---- epilogue 1: f = sigmoid(z1+bf); g = f*h -> A g-half ----
        int gra = base + wr*16 + r0;
        int grb = gra + 8;
        float fk[8][4], hk[8][4];
#pragma unroll
        for (int t = 0; t < 8; t++){
            int col = wc*64 + t*8 + tig*2;
            float2 bz = __ldg((const float2*)&bfp[col]);
            float2 ha = (gra < NN) ? __ldg((const float2*)&g_h[(size_t)gra*HH + col]) : make_float2(0.f,0.f);
            float2 hb = (grb < NN) ? __ldg((const float2*)&g_h[(size_t)grb*HH + col]) : make_float2(0.f,0.f);
            fk[t][0] = sigf(c[t][0] + bz.x);
            fk[t][1] = sigf(c[t][1] + bz.y);
            fk[t][2] = sigf(c[t][2] + bz.x);
            fk[t][3] = sigf(c[t][3] + bz.y);
            hk[t][0] = ha.x; hk[t][1] = ha.y; hk[t][2] = hb.x; hk[t][3] = hb.y;
            float ga0 = fk[t][0]*ha.x, ga1 = fk[t][1]*ha.y;
            float gb0 = fk[t][2]*hb.x, gb1 = fk[t][3]*hb.y;
            int lra = (wr*16 + r0)*WKW + 64 + (col >> 1);
            int lrb = lra + 8*WKW;
            uint32_t pa = pack_hi(ga0, ga1);
            uint32_t pb = pack_hi(gb0, gb1);
            float2 la = resid(ga0, ga1, pa);
            float2 lb = resid(gb0, gb1, pb);
            Ahi[lra] = pa; Alo[lra] = pack_hi(la.x, la.y);
            Ahi[lrb] = pb; Alo[lrb] = pack_hi(lb.x, lb.y);
        }
        CPA_WAIT0();
        __syncthreads();   // g visible + phase-2 weights landed

        // ---- GEMM2: z2 = [m|g] @ [Wh|Uh]^T ----
#pragma unroll
        for (int t = 0; t < 8; t++){ c[t][0]=0.f; c[t][1]=0.f; c[t][2]=0.f; c[t][3]=0.f; }
#pragma unroll 4
        for (int ks = 0; ks < 16; ks++){
            uint32_t ko = (uint32_t)(ks*32);
            uint32_t ah[4], al[4];
            ldmx4(ah, aHad + ko);
            ldmx4(al, aLad + ko);
#pragma unroll
            for (int p = 0; p < 4; p++){
                uint32_t bh[4], bl[4];
                ldmx4(bh, bHad[p] + ko);
                ldmx4(bl, bLad[p] + ko);
                mma_bf16(c[2*p],   ah, bh[0], bh[1]);
                mma_bf16(c[2*p],   al, bh[0], bh[1]);
                mma_bf16(c[2*p],   ah, bl[0], bl[1]);
                mma_bf16(c[2*p+1], ah, bh[2], bh[3]);
                mma_bf16(c[2*p+1], al, bh[2], bh[3]);
                mma_bf16(c[2*p+1], ah, bl[2], bl[3]);
            }
        }
        __syncthreads();   // A reads done before staging overwrite

        // ---- epilogue 2: h_new = (1-f)*h + f*tanh(z2+bh) -> stage in SMEM ----
        float* S = (float*)Ahi;
#pragma unroll
        for (int t = 0; t < 8; t++){
            int col = wc*64 + t*8 + tig*2;
            float2 bz = __ldg((const float2*)&bhp[col]);
            float t0 = tanhfast(c[t][0] + bz.x);
            float t1 = tanhfast(c[t][1] + bz.y);
            float t2 = tanhfast(c[t][2] + bz.x);
            float t3 = tanhfast(c[t][3] + bz.y);
            int lra = (wr*16 + r0)*WKW + col;
            int lrb = lra + 8*WKW;
            *(float2*)&S[lra] = make_float2((1.f-fk[t][0])*hk[t][0] + fk[t][0]*t0,
                                            (1.f-fk[t][1])*hk[t][1] + fk[t][1]*t1);
            *(float2*)&S[lrb] = make_float2((1.f-fk[t][2])*hk[t][2] + fk[t][2]*t2,
                                            (1.f-fk[t][3])*hk[t][3] + fk[t][3]*t3);
        }
        __syncthreads();

        // coalesced store h_new
#pragma unroll
        for (int i = 0; i < 8; i++){
            int q = tid + i*256;
            int row = q >> 5, c4 = q & 31;
            int gn = base + row;
            if (gn < NN){
                float4 v = *(float4*)&S[row*WKW + c4*4];
                ((float4*)g_h)[(size_t)gn*32 + c4] = v;
            }
        }
    }
}

// ---------------- fused Set2Set (3 steps LSTM+attn) + prediction ----------------
__global__ __launch_bounds__(256) void k_s2s(
    const float* __restrict__ wih, const float* __restrict__ whh,
    const float* __restrict__ bih, const float* __restrict__ bhh,
    const float* __restrict__ wp,  const float* __restrict__ bp,
    float* __restrict__ out)
{
    __shared__ __align__(16) float qs[2*HH];
    __shared__ __align__(16) float hl[HH];
    __shared__ __align__(16) float cl[HH];
    __shared__ float gt[4*HH];
    __shared__ float red[8];
    __shared__ __align__(16) float rp[8][HH];

    int g = blockIdx.x, t = threadIdx.x, wid = t >> 5, lane = t & 31;
    int s = g_bounds[g], e = g_bounds[g+1];
    const float4* h4 = (const float4*)g_h;

    if (t < HH){ hl[t] = 0.f; cl[t] = 0.f; }
    qs[t] = 0.f;
    __syncthreads();

    for (int step = 0; step < 3; step++){
        {
            const float4* qs4 = (const float4*)qs;
            const float4* hl4 = (const float4*)hl;
            float4 q0 = qs4[lane], q1 = qs4[32 + lane];
            float4 hh0 = hl4[lane];
            for (int r = wid*64; r < wid*64 + 64; r++){
                const float4* wr = (const float4*)(wih + (size_t)r*2*HH);
                const float4* hr = (const float4*)(whh + (size_t)r*HH);
                float4 w0 = __ldg(wr + lane);
                float4 w1 = __ldg(wr + 32 + lane);
                float4 h0 = __ldg(hr + lane);
                float p = w0.x*q0.x + w0.y*q0.y + w0.z*q0.z + w0.w*q0.w
                        + w1.x*q1.x + w1.y*q1.y + w1.z*q1.z + w1.w*q1.w
                        + h0.x*hh0.x + h0.y*hh0.y + h0.z*hh0.z + h0.w*hh0.w;
#pragma unroll
                for (int o = 16; o; o >>= 1) p += __shfl_xor_sync(0xffffffffu, p, o);
                if (lane == 0) gt[r] = p + __ldg(&bih[r]) + __ldg(&bhh[r]);
            }
        }
        __syncthreads();
        if (t < HH){
            float c = sigf(gt[HH+t])*cl[t] + sigf(gt[t])*tanhfast(gt[2*HH+t]);
            cl[t] = c;
            float hv = sigf(gt[3*HH+t])*tanhfast(c);
            hl[t] = hv;
            qs[t] = hv;
        }
        __syncthreads();

        float4 q4 = ((const float4*)hl)[lane];
        float lmax = -3.4e38f;
        for (int b = s + wid*4; b < e; b += 32){
            float p[4];
#pragma unroll
            for (int j = 0; j < 4; j++){
                if (b + j < e){
                    float4 x = __ldg(h4 + (size_t)(b+j)*32 + lane);
                    p[j] = x.x*q4.x + x.y*q4.y + x.z*q4.z + x.w*q4.w;
                } else p[j] = 0.f;
            }
#pragma unroll
            for (int o = 16; o; o >>= 1){
#pragma unroll
                for (int j = 0; j < 4; j++) p[j] += __shfl_xor_sync(0xffffffffu, p[j], o);
            }
#pragma unroll
            for (int j = 0; j < 4; j++){
                if (b + j < e){
                    if (lane == 0) g_e[b+j] = p[j];
                    lmax = fmaxf(lmax, p[j]);
                }
            }
        }
        if (lane == 0) red[wid] = lmax;
        __syncthreads();
        float emax = -3.4e38f;
#pragma unroll
        for (int w = 0; w < 8; w++) emax = fmaxf(emax, red[w]);
        __syncthreads();

        float lsum = 0.f;
        for (int n = s + t; n < e; n += 256){
            float w = __expf(g_e[n] - emax);
            g_e[n] = w;
            lsum += w;
        }
#pragma unroll
        for (int o = 16; o; o >>= 1) lsum += __shfl_xor_sync(0xffffffffu, lsum, o);
        if (lane == 0) red[wid] = lsum;
        __syncthreads();
        float denom = 0.f;
#pragma unroll
        for (int w = 0; w < 8; w++) denom += red[w];

        float4 racc = make_float4(0.f,0.f,0.f,0.f);
        for (int b = s + wid*4; b < e; b += 32){
#pragma unroll
            for (int j = 0; j < 4; j++){
                if (b + j < e){
                    float coef = __ldg(&g_e[b+j]);
                    float4 x = __ldg(h4 + (size_t)(b+j)*32 + lane);
                    racc.x += coef*x.x; racc.y += coef*x.y;
                    racc.z += coef*x.z; racc.w += coef*x.w;
                }
            }
        }
        ((float4*)rp[wid])[lane] = racc;
        __syncthreads();
        if (t < HH){
            float r = 0.f;
#pragma unroll
            for (int w = 0; w < 8; w++) r += rp[w][t];
            qs[HH + t] = (e > s) ? (r / denom) : 0.f;
        }
        __syncthreads();
    }

    float p = qs[t] * __ldg(&wp[t]);
#pragma unroll
    for (int o = 16; o; o >>= 1) p += __shfl_xor_sync(0xffffffffu, p, o);
    if (lane == 0) red[wid] = p;
    __syncthreads();
    if (t == 0){
        float r = 0.f;
#pragma unroll
        for (int w = 0; w < 8; w++) r += red[w];
        out[g] = r + __ldg(&bp[0]);
    }
}

// ---------------- launcher ----------------
extern "C" void kernel_launch(void* const* d_in, const int* in_sizes, int n_in,
                              void* d_out, int out_size){
    const float* x    = (const float*)d_in[0];
    const int*   ei   = (const int*)  d_in[1];
    const int*   batch= (const int*)  d_in[2];
    const float* Win  = (const float*)d_in[3];
    const float* bin  = (const float*)d_in[4];
    const float* Wf   = (const float*)d_in[5];
    const float* Uf   = (const float*)d_in[6];
    const float* bf   = (const float*)d_in[7];
    const float* Wh   = (const float*)d_in[8];
    const float* Uh   = (const float*)d_in[9];
    const float* bh   = (const float*)d_in[10];
    const float* wih  = (const float*)d_in[11];
    const float* whh  = (const float*)d_in[12];
    const float* bih  = (const float*)d_in[13];
    const float* bhh  = (const float*)d_in[14];
    const float* wp   = (const float*)d_in[15];
    const float* bp   = (const float*)d_in[16];
    float* out = (float*)d_out;

    cudaFuncSetAttribute(k_mgu_mma, cudaFuncAttributeMaxDynamicSharedMemorySize, SMF2);
    cudaFuncSetAttribute(k_input,   cudaFuncAttributeMaxDynamicSharedMemorySize, 49152);

    const int* esrc = ei;
    const int* edst = ei + NE;
    const int NB1K = (NN + 1023) / 1024;

    k_prepin<<<dim3(2,4), dim3(32,32)>>>(Win);
    k_prepw<<<(2*HH*2*WKW + 255)/256, 256>>>(Wf, Uf, Wh, Uh);
    k_bounds<<<(NN+255)/256, 256>>>(batch);

    k_hist<<<(NE+255)/256, 256>>>(edst);
    k_scan1<<<NB1K, 1024>>>();
    k_scan2<<<1, 128>>>(NB1K);
    k_scan3<<<(NN+255)/256, 256>>>();
    k_fill<<<(NE+255)/256, 256>>>(esrc, edst);

    k_input<<<(NN+63)/64, 256, 49152>>>(x, bin);

    for (int step = 0; step < 3; step++){
        k_agg<<<(NN*32 + 255)/256, 256>>>();
        k_mgu_mma<<<152, 256, SMF2>>>(bf, bh);
    }

    k_s2s<<<NG, 256>>>(wih, whh, bih, bhh, wp, bp, out);
}

// round 17
// speedup vs baseline: 1.5882x; 1.0175x over previous
#include <cuda_runtime.h>
#include <cuda_bf16.h>
#include <math.h>
#include <stdint.h>

#define NN 100000
#define NE 640000
#define IND 64
#define HH  128
#define NG  128

typedef unsigned long long u64;

// ---------------- scratch (static device globals) ----------------
__device__ float g_h [NN*HH];
__device__ float g_m [NN*HH];
__device__ float g_Wint[IND*HH];
__device__ float g_e  [NN];
__device__ int   g_bounds[NG+1];
// bf16 hi/lo weight images: [128 n][264 k] (k = W|U concat + 8 pad), per gate
#define WKW 132            // words (uint32 = 2 bf16) per row
__device__ uint32_t g_VFh[HH*WKW];
__device__ uint32_t g_VFl[HH*WKW];
__device__ uint32_t g_VHh[HH*WKW];
__device__ uint32_t g_VHl[HH*WKW];
// CSR scratch
__device__ int g_deg[NN];
__device__ int g_off[NN+1];
__device__ int g_csr[NE];
__device__ int g_bsum[128];

__device__ __forceinline__ float sigf(float z)   { return __fdividef(1.f, 1.f + __expf(-z)); }
__device__ __forceinline__ float tanhfast(float z){ return 1.f - __fdividef(2.f, __expf(2.f*z) + 1.f); }

// ---- packed fp32x2 helpers (FFMA2, for input layer) ----
__device__ __forceinline__ u64 dup2(float a){
    u64 r; asm("mov.b64 %0, {%1, %1};" : "=l"(r) : "f"(a)); return r;
}
__device__ __forceinline__ void ffma2(u64& d, u64 a, u64 b){
    asm("fma.rn.f32x2 %0, %1, %2, %0;" : "+l"(d) : "l"(a), "l"(b));
}
__device__ __forceinline__ float2 unpk(u64 v){
    float2 r; asm("mov.b64 {%0, %1}, %2;" : "=f"(r.x), "=f"(r.y) : "l"(v)); return r;
}

// ---- bf16 pack/resid ----
__device__ __forceinline__ uint32_t pack_hi(float lo, float hi_e){
    uint32_t r; asm("cvt.rn.bf16x2.f32 %0, %1, %2;" : "=r"(r) : "f"(hi_e), "f"(lo)); return r;
}
__device__ __forceinline__ float2 resid(float vx, float vy, uint32_t hp){
    float r0 = __uint_as_float(hp << 16);
    float r1 = __uint_as_float(hp & 0xFFFF0000u);
    return make_float2(vx - r0, vy - r1);
}

// ---- mma.sync bf16 ----
__device__ __forceinline__ void mma_bf16(float* c, const uint32_t* a, uint32_t b0, uint32_t b1){
    asm volatile("mma.sync.aligned.m16n8k16.row.col.f32.bf16.bf16.f32 "
        "{%0,%1,%2,%3}, {%4,%5,%6,%7}, {%8,%9}, {%0,%1,%2,%3};"
        : "+f"(c[0]), "+f"(c[1]), "+f"(c[2]), "+f"(c[3])
        : "r"(a[0]), "r"(a[1]), "r"(a[2]), "r"(a[3]), "r"(b0), "r"(b1));
}

// ---- ldmatrix x4 ----
__device__ __forceinline__ void ldmx4(uint32_t* r, uint32_t saddr){
    asm volatile("ldmatrix.sync.aligned.m8n8.x4.shared.b16 {%0,%1,%2,%3}, [%4];"
        : "=r"(r[0]), "=r"(r[1]), "=r"(r[2]), "=r"(r[3]) : "r"(saddr));
}

// ---- cp.async ----
__device__ __forceinline__ void cpa16(uint32_t saddr, const void* g){
    asm volatile("cp.async.cg.shared.global [%0], [%1], 16;" :: "r"(saddr), "l"(g) : "memory");
}
#define CPA_COMMIT() asm volatile("cp.async.commit_group;" ::: "memory")
#define CPA_WAIT0()  asm volatile("cp.async.wait_group 0;" ::: "memory")

// ---------------- weight prep: Win transpose (z=0) + bf16 hi/lo images (z=1) ----------------
__global__ void k_prep(const float* __restrict__ Win, const float* __restrict__ Wf,
                       const float* __restrict__ Uf,  const float* __restrict__ Wh,
                       const float* __restrict__ Uh){
    if (blockIdx.z == 0){
        __shared__ float t[32][33];
        int c = blockIdx.x*32 + threadIdx.x;
        int r = blockIdx.y*32 + threadIdx.y;
        int tid1 = threadIdx.y*32 + threadIdx.x; (void)tid1;
        if (blockIdx.x < 2 && blockIdx.y < 4){
            if (r < 128 && c < 64) t[threadIdx.y][threadIdx.x] = Win[r*64 + c];
            __syncthreads();
            int rc = blockIdx.x*32 + threadIdx.y;
            int cc = blockIdx.y*32 + threadIdx.x;
            if (rc < 64 && cc < 128) g_Wint[rc*128 + cc] = t[threadIdx.x][threadIdx.y];
        }
        return;
    }
    int idx = (blockIdx.y*gridDim.x + blockIdx.x)*1024 + threadIdx.y*32 + threadIdx.x;
    if (idx >= 2*HH*2*WKW) return;
    int gate = idx / (HH*2*WKW);
    int rem  = idx % (HH*2*WKW);
    int n = rem / (2*WKW);
    int k = rem % (2*WKW);
    float v = 0.f;
    if (k < 128)      v = (gate ? Wh : Wf)[n*128 + k];
    else if (k < 256) v = (gate ? Uh : Uf)[n*128 + (k-128)];
    __nv_bfloat16 hb = __float2bfloat16(v);
    float lo = v - __bfloat162float(hb);
    __nv_bfloat16 lb = __float2bfloat16(lo);
    __nv_bfloat16* H = (__nv_bfloat16*)(gate ? g_VHh : g_VFh);
    __nv_bfloat16* L = (__nv_bfloat16*)(gate ? g_VHl : g_VFl);
    H[n*2*WKW + k] = hb;
    L[n*2*WKW + k] = lb;
}

// ---------------- bounds + zero deg ----------------
__global__ void k_bounds(const int* __restrict__ batch){
    int i = blockIdx.x*blockDim.x + threadIdx.x;
    if (i < NN) g_deg[i] = 0;
    if (i >= NN) return;
    int b = batch[i];
    if (i == 0)      { for (int g = 0;    g <= b;  g++) g_bounds[g] = 0; }
    else             { int pb = batch[i-1];
                       for (int g = pb+1; g <= b;  g++) g_bounds[g] = i; }
    if (i == NN-1)   { for (int g = b+1;  g <= NG; g++) g_bounds[g] = NN; }
}

// ---------------- CSR build ----------------
__global__ void k_hist(const int* __restrict__ dst){
    int e = blockIdx.x*blockDim.x + threadIdx.x;
    if (e < NE) atomicAdd(&g_deg[dst[e]], 1);
}
__global__ __launch_bounds__(1024) void k_scan1(){
    __shared__ int sd[1024];
    int t = threadIdx.x, i = blockIdx.x*1024 + t;
    int v = (i < NN) ? g_deg[i] : 0;
    sd[t] = v; __syncthreads();
#pragma unroll
    for (int o = 1; o < 1024; o <<= 1){
        int x = (t >= o) ? sd[t-o] : 0;
        __syncthreads();
        sd[t] += x;
        __syncthreads();
    }
    if (i < NN) g_off[i] = sd[t] - v;
    if (t == 1023) g_bsum[blockIdx.x] = sd[1023];
}
__global__ __launch_bounds__(128) void k_scan2(int nb){
    __shared__ int sd[128];
    int t = threadIdx.x;
    int v = (t < nb) ? g_bsum[t] : 0;
    sd[t] = v; __syncthreads();
#pragma unroll
    for (int o = 1; o < 128; o <<= 1){
        int x = (t >= o) ? sd[t-o] : 0;
        __syncthreads();
        sd[t] += x;
        __syncthreads();
    }
    if (t < nb) g_bsum[t] = sd[t] - v;
}
__global__ void k_scan3(){
    int i = blockIdx.x*blockDim.x + threadIdx.x;
    if (i < NN){ int o = g_off[i] + g_bsum[i >> 10]; g_off[i] = o; g_deg[i] = o; }
    if (i == 0) g_off[NN] = NE;
}
__global__ void k_fill(const int* __restrict__ src, const int* __restrict__ dst){
    int e = blockIdx.x*blockDim.x + threadIdx.x;
    if (e >= NE) return;
    int pos = atomicAdd(&g_deg[dst[e]], 1);
    g_csr[pos] = src[e];
}

// ---------------- aggregation: warp per node, unroll-2 ----------------
__global__ __launch_bounds__(256) void k_agg(){
    int w = (blockIdx.x*blockDim.x + threadIdx.x) >> 5;
    if (w >= NN) return;
    int lane = threadIdx.x & 31;
    int s = __ldg(&g_off[w]), e = __ldg(&g_off[w+1]);
    const float4* h4 = (const float4*)g_h;
    float4 acc = make_float4(0.f,0.f,0.f,0.f);
    int p = s;
    for (; p + 1 < e; p += 2){
        int s0 = __ldg(&g_csr[p]);
        int s1 = __ldg(&g_csr[p+1]);
        float4 v0 = __ldg(h4 + (size_t)s0*32 + lane);
        float4 v1 = __ldg(h4 + (size_t)s1*32 + lane);
        acc.x += v0.x; acc.y += v0.y; acc.z += v0.z; acc.w += v0.w;
        acc.x += v1.x; acc.y += v1.y; acc.z += v1.z; acc.w += v1.w;
    }
    if (p < e){
        int s0 = __ldg(&g_csr[p]);
        float4 v0 = __ldg(h4 + (size_t)s0*32 + lane);
        acc.x += v0.x; acc.y += v0.y; acc.z += v0.z; acc.w += v0.w;
    }
    ((float4*)g_m)[(size_t)w*32 + lane] = acc;
}

// ---------------- input layer (FFMA2) ----------------
__global__ __launch_bounds__(256) void k_input(const float* __restrict__ x,
                                               const float* __restrict__ bin){
    extern __shared__ float sm[];
    float4* Ws4 = (float4*)sm;
    float4* Xs4 = (float4*)(sm + IND*HH);
    int tid = threadIdx.x;
    int jt = tid & 31, nt = tid >> 5;

    const float4* Wg = (const float4*)g_Wint;
#pragma unroll
    for (int i = 0; i < 8; i++) Ws4[tid + i*256] = Wg[tid + i*256];

    int base = blockIdx.x * 64;
    const float4* Xg = (const float4*)x;
#pragma unroll
    for (int i = 0; i < 4; i++){
        int q = tid + i*256;
        int rn = q >> 4, col = q & 15;
        int gn = base + rn;
        Xs4[q] = (gn < NN) ? Xg[gn*16 + col] : make_float4(0.f,0.f,0.f,0.f);
    }
    __syncthreads();

    u64 acc[8][2];
#pragma unroll
    for (int i = 0; i < 8; i++){ acc[i][0] = 0ull; acc[i][1] = 0ull; }

    for (int k = 0; k < IND; k += 4){
        float a[8][4];
#pragma unroll
        for (int i = 0; i < 8; i++){
            float4 t4 = Xs4[(nt*8+i)*16 + (k>>2)];
            a[i][0]=t4.x; a[i][1]=t4.y; a[i][2]=t4.z; a[i][3]=t4.w;
        }
#pragma unroll
        for (int kk = 0; kk < 4; kk++){
            ulonglong2 wv = ((const ulonglong2*)Ws4)[(k+kk)*32 + jt];
#pragma unroll
            for (int i = 0; i < 8; i++){
                u64 a2 = dup2(a[i][kk]);
                ffma2(acc[i][0], a2, wv.x);
                ffma2(acc[i][1], a2, wv.y);
            }
        }
    }
    float4 bb = ((const float4*)bin)[jt];
#pragma unroll
    for (int i = 0; i < 8; i++){
        int n = base + nt*8 + i;
        if (n < NN){
            float2 z01 = unpk(acc[i][0]);
            float2 z23 = unpk(acc[i][1]);
            float4 o;
            o.x = fmaxf(z01.x+bb.x, 0.f);
            o.y = fmaxf(z01.y+bb.y, 0.f);
            o.z = fmaxf(z23.x+bb.z, 0.f);
            o.w = fmaxf(z23.y+bb.w, 0.f);
            ((float4*)g_h)[n*32 + jt] = o;
        }
    }
}

// ---------------- fused MGU step via bf16-split mma.sync + ldmatrix ----------------
#define OFF_WHI 0
#define OFF_WLO (HH*WKW)
#define OFF_AHI (2*HH*WKW)
#define OFF_ALO (2*HH*WKW + 64*WKW)
#define SMW_TOT (2*HH*WKW + 2*64*WKW)
#define SMF2 (SMW_TOT*4)
#define WCP 4224   // 16B chunks per weight image (128*132*4/16)

__global__ __launch_bounds__(256, 1) void k_mgu_mma(
    const float* __restrict__ bfp, const float* __restrict__ bhp)
{
    extern __shared__ uint32_t smw[];
    uint32_t* Whi = smw + OFF_WHI;
    uint32_t* Wlo = smw + OFF_WLO;
    uint32_t* Ahi = smw + OFF_AHI;
    uint32_t* Alo = smw + OFF_ALO;
    uint32_t whi_sa = (uint32_t)__cvta_generic_to_shared(Whi);
    uint32_t wlo_sa = (uint32_t)__cvta_generic_to_shared(Wlo);
    uint32_t ahi_sa = (uint32_t)__cvta_generic_to_shared(Ahi);
    uint32_t alo_sa = (uint32_t)__cvta_generic_to_shared(Alo);

    int tid = threadIdx.x;
    int lane = tid & 31, wid = tid >> 5;
    int wr = wid & 3;          // m-row group (16 rows)
    int wc = wid >> 2;         // col group (64 cols)
    int r0 = lane >> 2;        // 0..7
    int tig = lane & 3;        // 0..3

    // ldmatrix lane addressing (tile-invariant)
    int j8 = lane >> 3, l7 = lane & 7;
    uint32_t a_row = (uint32_t)(wr*16 + ((j8 & 1) << 3) + l7);
    uint32_t a_off = (a_row*WKW + ((j8 >> 1) << 2)) * 4u;
    uint32_t aHad = ahi_sa + a_off;
    uint32_t aLad = alo_sa + a_off;
    uint32_t bHad[4], bLad[4];
#pragma unroll
    for (int p = 0; p < 4; p++){
        uint32_t b_row = (uint32_t)(wc*64 + (2*p + (j8 >> 1))*8 + l7);
        uint32_t b_off = (b_row*WKW + ((j8 & 1) << 2)) * 4u;
        bHad[p] = whi_sa + b_off;
        bLad[p] = wlo_sa + b_off;
    }

    const float4* Mg = (const float4*)g_m;
    const float4* Hg = (const float4*)g_h;

    int ntiles = (NN + 63) >> 6;

    for (int tile = blockIdx.x; tile < ntiles; tile += gridDim.x){
        int base = tile << 6;
        __syncthreads();   // previous tile fully done

        // issue phase-1 weight copies (f-gate)
#pragma unroll
        for (int i = 0; i < 17; i++){
            int q = tid + i*256;
            if (q < WCP){
                cpa16(whi_sa + q*16, (const char*)g_VFh + q*16);
                cpa16(wlo_sa + q*16, (const char*)g_VFl + q*16);
            }
        }
        CPA_COMMIT();

        // A-tile conversion: [m|h] fp32 -> bf16 hi/lo
#pragma unroll
        for (int i = 0; i < 16; i++){
            int q = tid + i*256;
            int row = q >> 6, c4 = q & 63;
            int gn = base + row;
            float4 v = make_float4(0.f,0.f,0.f,0.f);
            if (gn < NN) v = (c4 < 32) ? __ldg(Mg + (size_t)gn*32 + c4)
                                       : __ldg(Hg + (size_t)gn*32 + (c4-32));
            uint32_t h0 = pack_hi(v.x, v.y);
            uint32_t h1 = pack_hi(v.z, v.w);
            float2 l0 = resid(v.x, v.y, h0);
            float2 l1 = resid(v.z, v.w, h1);
            int wbase = row*WKW + 2*c4;
            Ahi[wbase]   = h0;
            Ahi[wbase+1] = h1;
            Alo[wbase]   = pack_hi(l0.x, l0.y);
            Alo[wbase+1] = pack_hi(l1.x, l1.y);
        }
        CPA_WAIT0();
        __syncthreads();

        // ---- GEMM1: z1 = [m|h] @ [Wf|Uf]^T ----
        float c[8][4];
#pragma unroll
        for (int t = 0; t < 8; t++){ c[t][0]=0.f; c[t][1]=0.f; c[t][2]=0.f; c[t][3]=0.f; }
#pragma unroll 4
        for (int ks = 0; ks < 16; ks++){
            uint32_t ko = (uint32_t)(ks*32);
            uint32_t ah[4], al[4];
            ldmx4(ah, aHad + ko);
            ldmx4(al, aLad + ko);
#pragma unroll
            for (int p = 0; p < 4; p++){
                uint32_t bh[4], bl[4];
                ldmx4(bh, bHad[p] + ko);
                ldmx4(bl, bLad[p] + ko);
                mma_bf16(c[2*p],   ah, bh[0], bh[1]);
                mma_bf16(c[2*p],   al, bh[0], bh[1]);
                mma_bf16(c[2*p],   ah, bl[0], bl[1]);
                mma_bf16(c[2*p+1], ah, bh[2], bh[3]);
                mma_bf16(c[2*p+1], al, bh[2], bh[3]);
                mma_bf16(c[2*p+1], ah, bl[2], bl[3]);
            }
        }
        __syncthreads();   // all warps done reading phase-1 weights

        // issue phase-2 weight copies (h-gate)
#pragma unroll
        for (int i = 0; i < 17; i++){
            int q = tid + i*256;
            if (q < WCP){
                cpa16(whi_sa + q*16, (const char*)g_VHh + q*16);
                cpa16(wlo_sa + q*16, (const char*)g_VHl + q*16);
            }
        }
        CPA_COMMIT();

        // ---- epilogue 1: f = sigmoid(z1+bf); h from SMEM (hi+lo); g = f*h ----
        float fk[8][4], hk[8][4];
#pragma unroll
        for (int t = 0; t < 8; t++){
            int col = wc*64 + t*8 + tig*2;
            float2 bz = __ldg((const float2*)&bfp[col]);
            int lra = (wr*16 + r0)*WKW + 64 + (col >> 1);
            int lrb = lra + 8*WKW;
            uint32_t wa = Ahi[lra], la = Alo[lra];
            uint32_t wb = Ahi[lrb], lb = Alo[lrb];
            float ha0 = __uint_as_float(wa << 16)          + __uint_as_float(la << 16);
            float ha1 = __uint_as_float(wa & 0xFFFF0000u)  + __uint_as_float(la & 0xFFFF0000u);
            float hb0 = __uint_as_float(wb << 16)          + __uint_as_float(lb << 16);
            float hb1 = __uint_as_float(wb & 0xFFFF0000u)  + __uint_as_float(lb & 0xFFFF0000u);
            fk[t][0] = sigf(c[t][0] + bz.x);
            fk[t][1] = sigf(c[t][1] + bz.y);
            fk[t][2] = sigf(c[t][2] + bz.x);
            fk[t][3] = sigf(c[t][3] + bz.y);
            hk[t][0] = ha0; hk[t][1] = ha1; hk[t][2] = hb0; hk[t][3] = hb1;
            float ga0 = fk[t][0]*ha0, ga1 = fk[t][1]*ha1;
            float gb0 = fk[t][2]*hb0, gb1 = fk[t][3]*hb1;
            uint32_t pa = pack_hi(ga0, ga1);
            uint32_t pb = pack_hi(gb0, gb1);
            float2 ra = resid(ga0, ga1, pa);
            float2 rb = resid(gb0, gb1, pb);
            Ahi[lra] = pa; Alo[lra] = pack_hi(ra.x, ra.y);
            Ahi[lrb] = pb; Alo[lrb] = pack_hi(rb.x, rb.y);
        }
        CPA_WAIT0();
        __syncthreads();   // g visible + phase-2 weights landed

        // ---- GEMM2: z2 = [m|g] @ [Wh|Uh]^T ----
#pragma unroll
        for (int t = 0; t < 8; t++){ c[t][0]=0.f; c[t][1]=0.f; c[t][2]=0.f; c[t][3]=0.f; }
#pragma unroll 4
        for (int ks = 0; ks < 16; ks++){
            uint32_t ko = (uint32_t)(ks*32);
            uint32_t ah[4], al[4];
            ldmx4(ah, aHad + ko);
            ldmx4(al, aLad + ko);
#pragma unroll
            for (int p = 0; p < 4; p++){
                uint32_t bh[4], bl[4];
                ldmx4(bh, bHad[p] + ko);
                ldmx4(bl, bLad[p] + ko);
                mma_bf16(c[2*p],   ah, bh[0], bh[1]);
                mma_bf16(c[2*p],   al, bh[0], bh[1]);
                mma_bf16(c[2*p],   ah, bl[0], bl[1]);
                mma_bf16(c[2*p+1], ah, bh[2], bh[3]);
                mma_bf16(c[2*p+1], al, bh[2], bh[3]);
                mma_bf16(c[2*p+1], ah, bl[2], bl[3]);
            }
        }
        __syncthreads();   // A reads done before staging overwrite

        // ---- epilogue 2: h_new = (1-f)*h + f*tanh(z2+bh) -> stage in SMEM ----
        float* S = (float*)Ahi;
#pragma unroll
        for (int t = 0; t < 8; t++){
            int col = wc*64 + t*8 + tig*2;
            float2 bz = __ldg((const float2*)&bhp[col]);
            float t0 = tanhfast(c[t][0] + bz.x);
            float t1 = tanhfast(c[t][1] + bz.y);
            float t2 = tanhfast(c[t][2] + bz.x);
            float t3 = tanhfast(c[t][3] + bz.y);
            int lra = (wr*16 + r0)*WKW + col;
            int lrb = lra + 8*WKW;
            *(float2*)&S[lra] = make_float2((1.f-fk[t][0])*hk[t][0] + fk[t][0]*t0,
                                            (1.f-fk[t][1])*hk[t][1] + fk[t][1]*t1);
            *(float2*)&S[lrb] = make_float2((1.f-fk[t][2])*hk[t][2] + fk[t][2]*t2,
                                            (1.f-fk[t][3])*hk[t][3] + fk[t][3]*t3);
        }
        __syncthreads();

        // coalesced store h_new
#pragma unroll
        for (int i = 0; i < 8; i++){
            int q = tid + i*256;
            int row = q >> 5, c4 = q & 31;
            int gn = base + row;
            if (gn < NN){
                float4 v = *(float4*)&S[row*WKW + c4*4];
                ((float4*)g_h)[(size_t)gn*32 + c4] = v;
            }
        }
    }
}

// ---------------- fused Set2Set (3 steps LSTM+attn) + prediction ----------------
__global__ __launch_bounds__(256) void k_s2s(
    const float* __restrict__ wih, const float* __restrict__ whh,
    const float* __restrict__ bih, const float* __restrict__ bhh,
    const float* __restrict__ wp,  const float* __restrict__ bp,
    float* __restrict__ out)
{
    __shared__ __align__(16) float qs[2*HH];
    __shared__ __align__(16) float hl[HH];
    __shared__ __align__(16) float cl[HH];
    __shared__ float gt[4*HH];
    __shared__ float red[8];
    __shared__ __align__(16) float rp[8][HH];

    int g = blockIdx.x, t = threadIdx.x, wid = t >> 5, lane = t & 31;
    int s = g_bounds[g], e = g_bounds[g+1];
    const float4* h4 = (const float4*)g_h;

    if (t < HH){ hl[t] = 0.f; cl[t] = 0.f; }
    qs[t] = 0.f;
    __syncthreads();

    for (int step = 0; step < 3; step++){
        {
            const float4* qs4 = (const float4*)qs;
            const float4* hl4 = (const float4*)hl;
            float4 q0 = qs4[lane], q1 = qs4[32 + lane];
            float4 hh0 = hl4[lane];
            for (int r = wid*64; r < wid*64 + 64; r++){
                const float4* wr = (const float4*)(wih + (size_t)r*2*HH);
                const float4* hr = (const float4*)(whh + (size_t)r*HH);
                float4 w0 = __ldg(wr + lane);
                float4 w1 = __ldg(wr + 32 + lane);
                float4 h0 = __ldg(hr + lane);
                float p = w0.x*q0.x + w0.y*q0.y + w0.z*q0.z + w0.w*q0.w
                        + w1.x*q1.x + w1.y*q1.y + w1.z*q1.z + w1.w*q1.w
                        + h0.x*hh0.x + h0.y*hh0.y + h0.z*hh0.z + h0.w*hh0.w;
#pragma unroll
                for (int o = 16; o; o >>= 1) p += __shfl_xor_sync(0xffffffffu, p, o);
                if (lane == 0) gt[r] = p + __ldg(&bih[r]) + __ldg(&bhh[r]);
            }
        }
        __syncthreads();
        if (t < HH){
            float c = sigf(gt[HH+t])*cl[t] + sigf(gt[t])*tanhfast(gt[2*HH+t]);
            cl[t] = c;
            float hv = sigf(gt[3*HH+t])*tanhfast(c);
            hl[t] = hv;
            qs[t] = hv;
        }
        __syncthreads();

        float4 q4 = ((const float4*)hl)[lane];
        float lmax = -3.4e38f;
        for (int b = s + wid*4; b < e; b += 32){
            float p[4];
#pragma unroll
            for (int j = 0; j < 4; j++){
                if (b + j < e){
                    float4 x = __ldg(h4 + (size_t)(b+j)*32 + lane);
                    p[j] = x.x*q4.x + x.y*q4.y + x.z*q4.z + x.w*q4.w;
                } else p[j] = 0.f;
            }
#pragma unroll
            for (int o = 16; o; o >>= 1){
#pragma unroll
                for (int j = 0; j < 4; j++) p[j] += __shfl_xor_sync(0xffffffffu, p[j], o);
            }
#pragma unroll
            for (int j = 0; j < 4; j++){
                if (b + j < e){
                    if (lane == 0) g_e[b+j] = p[j];
                    lmax = fmaxf(lmax, p[j]);
                }
            }
        }
        if (lane == 0) red[wid] = lmax;
        __syncthreads();
        float emax = -3.4e38f;
#pragma unroll
        for (int w = 0; w < 8; w++) emax = fmaxf(emax, red[w]);
        __syncthreads();

        float lsum = 0.f;
        for (int n = s + t; n < e; n += 256){
            float w = __expf(g_e[n] - emax);
            g_e[n] = w;
            lsum += w;
        }
#pragma unroll
        for (int o = 16; o; o >>= 1) lsum += __shfl_xor_sync(0xffffffffu, lsum, o);
        if (lane == 0) red[wid] = lsum;
        __syncthreads();
        float denom = 0.f;
#pragma unroll
        for (int w = 0; w < 8; w++) denom += red[w];

        float4 racc = make_float4(0.f,0.f,0.f,0.f);
        for (int b = s + wid*4; b < e; b += 32){
#pragma unroll
            for (int j = 0; j < 4; j++){
                if (b + j < e){
                    float coef = __ldg(&g_e[b+j]);
                    float4 x = __ldg(h4 + (size_t)(b+j)*32 + lane);
                    racc.x += coef*x.x; racc.y += coef*x.y;
                    racc.z += coef*x.z; racc.w += coef*x.w;
                }
            }
        }
        ((float4*)rp[wid])[lane] = racc;
        __syncthreads();
        if (t < HH){
            float r = 0.f;
#pragma unroll
            for (int w = 0; w < 8; w++) r += rp[w][t];
            qs[HH + t] = (e > s) ? (r / denom) : 0.f;
        }
        __syncthreads();
    }

    float p = qs[t] * __ldg(&wp[t]);
#pragma unroll
    for (int o = 16; o; o >>= 1) p += __shfl_xor_sync(0xffffffffu, p, o);
    if (lane == 0) red[wid] = p;
    __syncthreads();
    if (t == 0){
        float r = 0.f;
#pragma unroll
        for (int w = 0; w < 8; w++) r += red[w];
        out[g] = r + __ldg(&bp[0]);
    }
}

// ---------------- launcher ----------------
extern "C" void kernel_launch(void* const* d_in, const int* in_sizes, int n_in,
                              void* d_out, int out_size){
    const float* x    = (const float*)d_in[0];
    const int*   ei   = (const int*)  d_in[1];
    const int*   batch= (const int*)  d_in[2];
    const float* Win  = (const float*)d_in[3];
    const float* bin  = (const float*)d_in[4];
    const float* Wf   = (const float*)d_in[5];
    const float* Uf   = (const float*)d_in[6];
    const float* bf   = (const float*)d_in[7];
    const float* Wh   = (const float*)d_in[8];
    const float* Uh   = (const float*)d_in[9];
    const float* bh   = (const float*)d_in[10];
    const float* wih  = (const float*)d_in[11];
    const float* whh  = (const float*)d_in[12];
    const float* bih  = (const float*)d_in[13];
    const float* bhh  = (const float*)d_in[14];
    const float* wp   = (const float*)d_in[15];
    const float* bp   = (const float*)d_in[16];
    float* out = (float*)d_out;

    cudaFuncSetAttribute(k_mgu_mma, cudaFuncAttributeMaxDynamicSharedMemorySize, SMF2);
    cudaFuncSetAttribute(k_input,   cudaFuncAttributeMaxDynamicSharedMemorySize, 49152);

    const int* esrc = ei;
    const int* edst = ei + NE;
    const int NB1K = (NN + 1023) / 1024;

    // z=0: Win transpose (uses 2x4 of the 9x8 grid); z=1: bf16 image build (66 kwords over 72 blocks)
    k_prep<<<dim3(9,8,2), dim3(32,32)>>>(Win, Wf, Uf, Wh, Uh);
    k_bounds<<<(NN+255)/256, 256>>>(batch);

    k_hist<<<(NE+255)/256, 256>>>(edst);
    k_scan1<<<NB1K, 1024>>>();
    k_scan2<<<1, 128>>>(NB1K);
    k_scan3<<<(NN+255)/256, 256>>>();
    k_fill<<<(NE+255)/256, 256>>>(esrc, edst);

    k_input<<<(NN+63)/64, 256, 49152>>>(x, bin);

    for (int step = 0; step < 3; step++){
        k_agg<<<(NN*32 + 255)/256, 256>>>();
        k_mgu_mma<<<152, 256, SMF2>>>(bf, bh);
    }

    k_s2s<<<NG, 256>>>(wih, whh, bih, bhh, wp, bp, out);
}